// round 13
// baseline (speedup 1.0000x reference)
#include <cuda_runtime.h>
#include <math.h>
#include <float.h>

// ---------------- problem constants ----------------
#define NN   2048
#define DIN  512
#define HID  256
#define NH   4
#define TOPK 6      // k+1
#define MAXD 2048   // no truncation (kNN hubness gives in-degrees in the hundreds)
#define BKK  16

// ---------------- device scratch (static, no allocs; zero-initialized) ----------------
__device__ float g_zero[NN];       // stays all-zero
__device__ float g_sqU[NN];
__device__ float g_XnF[NN*DIN];
__device__ float g_simU[NN*NN];
__device__ float g_simF[NN*NN];
__device__ int   g_tidxU[NN*TOPK];
__device__ float g_tvalU[NN*TOPK];
__device__ int   g_tidxF[NN*TOPK];
__device__ float g_tvalF[NN*TOPK];
__device__ unsigned char g_maskU[NN*NN];
__device__ unsigned char g_maskF[NN*NN];
__device__ int   g_nbrU[NN*MAXD];
__device__ int   g_cntU[NN];
__device__ int   g_nbrF[NN*MAXD];
__device__ int   g_cntF[NN];
// tf32 split buffers
__device__ float g_uhi[NN*DIN];
__device__ float g_ulo[NN*DIN];
__device__ float g_fhi[NN*DIN];
__device__ float g_flo[NN*DIN];
__device__ float g_xhi[NN*DIN];
__device__ float g_xlo[NN*DIN];
__device__ float g_WhiU[DIN*NH*HID];
__device__ float g_WloU[DIN*NH*HID];
__device__ float g_WhiF[DIN*NH*HID];
__device__ float g_WloF[DIN*NH*HID];
__device__ float g_WhU[NN*NH*HID];
__device__ float g_WhF[NN*NH*HID];
__device__ float g_s1U[NH*NN];
__device__ float g_s2U[NH*NN];
__device__ float g_s1F[NH*NN];
__device__ float g_s2F[NH*NN];
__device__ float g_hidU[NN*NH*HID];
__device__ float g_hidF[NN*NH*HID];
__device__ float g_WhoU[NN*HID];
__device__ float g_WhoF[NN*HID];
__device__ float g_s1oU[NN];
__device__ float g_s2oU[NN];
__device__ float g_s1oF[NN];
__device__ float g_s2oF[NN];
__device__ float g_embU[NN*HID];
__device__ float g_embF[NN*HID];
__device__ float g_pair[NN*512];
__device__ float g_act0[NN*512];
__device__ float g_act1[NN*256];
__device__ float g_act2[NN*128];

__device__ __forceinline__ float tf32r(float x)
{
    float y;
    asm("cvt.rna.tf32.f32 %0, %1;" : "=f"(y) : "f"(x));
    return y;
}

#define MMA_TF32(c, a0, a1, a2, a3, b0, b1) \
    asm volatile("mma.sync.aligned.m16n8k8.row.col.f32.tf32.tf32.f32 " \
                 "{%0,%1,%2,%3}, {%4,%5,%6,%7}, {%8,%9}, {%0,%1,%2,%3};" \
                 : "+f"(c[0]), "+f"(c[1]), "+f"(c[2]), "+f"(c[3]) \
                 : "r"(a0), "r"(a1), "r"(a2), "r"(a3), "r"(b0), "r"(b1))

// ---------------- tensor-core GEMM: 3xTF32 split emulation of fp32 ----------------
// Tile 128x128, 256 threads = 8 warps (2m x 4n of 64x32 warp tiles), K-slab 16.
// Inputs pre-split: X = Xhi + Xlo (tf32 each); acc += lo*hi + hi*lo + hi*hi.
// TB=false: C = A[M,K]*B[K,Nn]; TB=true: C = A[M,K]*B[Nn,K]^T
// EP: 0 none; 1 negd2 = -((sq[row]+sq[col]) - 2*acc)
// SYM: upper-tri tile enumeration + smem-staged coalesced mirror writes.
template<bool TB, int EP, bool SYM>
__launch_bounds__(256)
__global__ void mma_gemm2(const float* __restrict__ Ah0, const float* __restrict__ Al0,
                          const float* __restrict__ Bh0, const float* __restrict__ Bl0,
                          float* __restrict__ C0, const float* __restrict__ sq0,
                          const float* __restrict__ Ah1, const float* __restrict__ Al1,
                          const float* __restrict__ Bh1, const float* __restrict__ Bl1,
                          float* __restrict__ C1, const float* __restrict__ sq1,
                          int M, int Nn, int Kk, int lda, int ldb, int ldc)
{
    const float* Ah = blockIdx.z ? Ah1 : Ah0;
    const float* Al = blockIdx.z ? Al1 : Al0;
    const float* Bh = blockIdx.z ? Bh1 : Bh0;
    const float* Bl = blockIdx.z ? Bl1 : Bl0;
    float*       C  = blockIdx.z ? C1 : C0;
    const float* sq = blockIdx.z ? sq1 : sq0;

    __shared__ float smemS[4*BKK*132];          // 33792 B
    float (*AsHi)[132] = reinterpret_cast<float(*)[132]>(smemS);
    float (*AsLo)[132] = reinterpret_cast<float(*)[132]>(smemS + BKK*132);
    float (*BsHi)[132] = reinterpret_cast<float(*)[132]>(smemS + 2*BKK*132);
    float (*BsLo)[132] = reinterpret_cast<float(*)[132]>(smemS + 3*BKK*132);

    const int tid = threadIdx.x;
    const int wid = tid >> 5, lane = tid & 31;
    const int g = lane >> 2, t4 = lane & 3;
    const int wm = (wid >> 2) * 64;     // warp m offset in tile
    const int wn = (wid & 3) * 32;      // warp n offset

    int bx = blockIdx.x, by = blockIdx.y;
    if (SYM) {
        int nb = M / 128;
        int idx = blockIdx.x, bi = 0;
        while (idx >= nb - bi) { idx -= nb - bi; bi++; }
        by = bi; bx = bi + idx;
    }
    const int m0 = by * 128, n0 = bx * 128;

    float4 rah[2], ral[2], rbh[2], rbl[2];
    auto LOADAB = [&](int k0) {
#pragma unroll
        for (int it = 0; it < 2; it++) {
            int q = tid + it*256;
            int r = q >> 2, c4 = (q & 3) * 4;
            rah[it] = *(const float4*)(Ah + (size_t)(m0 + r)*lda + k0 + c4);
            ral[it] = *(const float4*)(Al + (size_t)(m0 + r)*lda + k0 + c4);
            if (TB) {
                rbh[it] = *(const float4*)(Bh + (size_t)(n0 + r)*ldb + k0 + c4);
                rbl[it] = *(const float4*)(Bl + (size_t)(n0 + r)*ldb + k0 + c4);
            } else {
                int rr = q >> 5, cn = (q & 31) * 4;
                rbh[it] = *(const float4*)(Bh + (size_t)(k0 + rr)*ldb + n0 + cn);
                rbl[it] = *(const float4*)(Bl + (size_t)(k0 + rr)*ldb + n0 + cn);
            }
        }
    };
    auto STOREAB = [&]() {
#pragma unroll
        for (int it = 0; it < 2; it++) {
            int q = tid + it*256;
            int r = q >> 2, c4 = (q & 3) * 4;
            AsHi[c4+0][r] = rah[it].x; AsHi[c4+1][r] = rah[it].y;
            AsHi[c4+2][r] = rah[it].z; AsHi[c4+3][r] = rah[it].w;
            AsLo[c4+0][r] = ral[it].x; AsLo[c4+1][r] = ral[it].y;
            AsLo[c4+2][r] = ral[it].z; AsLo[c4+3][r] = ral[it].w;
            if (TB) {
                BsHi[c4+0][r] = rbh[it].x; BsHi[c4+1][r] = rbh[it].y;
                BsHi[c4+2][r] = rbh[it].z; BsHi[c4+3][r] = rbh[it].w;
                BsLo[c4+0][r] = rbl[it].x; BsLo[c4+1][r] = rbl[it].y;
                BsLo[c4+2][r] = rbl[it].z; BsLo[c4+3][r] = rbl[it].w;
            } else {
                int rr = q >> 5, cn = (q & 31) * 4;
                BsHi[rr][cn+0] = rbh[it].x; BsHi[rr][cn+1] = rbh[it].y;
                BsHi[rr][cn+2] = rbh[it].z; BsHi[rr][cn+3] = rbh[it].w;
                BsLo[rr][cn+0] = rbl[it].x; BsLo[rr][cn+1] = rbl[it].y;
                BsLo[rr][cn+2] = rbl[it].z; BsLo[rr][cn+3] = rbl[it].w;
            }
        }
    };

    float acc[4][4][4];
#pragma unroll
    for (int i = 0; i < 4; i++)
#pragma unroll
        for (int j = 0; j < 4; j++)
#pragma unroll
            for (int e = 0; e < 4; e++) acc[i][j][e] = 0.f;

    auto COMPUTE = [&]() {
#pragma unroll
        for (int ks = 0; ks < BKK; ks += 8) {
            unsigned bh[4][2], bl[4][2];
#pragma unroll
            for (int nt = 0; nt < 4; nt++) {
                int cb = wn + 8*nt + g;
                bh[nt][0] = __float_as_uint(BsHi[ks + t4][cb]);
                bh[nt][1] = __float_as_uint(BsHi[ks + t4 + 4][cb]);
                bl[nt][0] = __float_as_uint(BsLo[ks + t4][cb]);
                bl[nt][1] = __float_as_uint(BsLo[ks + t4 + 4][cb]);
            }
#pragma unroll
            for (int mt = 0; mt < 4; mt++) {
                int rb = wm + 16*mt + g;
                unsigned ah0 = __float_as_uint(AsHi[ks + t4][rb]);
                unsigned ah1 = __float_as_uint(AsHi[ks + t4][rb + 8]);
                unsigned ah2 = __float_as_uint(AsHi[ks + t4 + 4][rb]);
                unsigned ah3 = __float_as_uint(AsHi[ks + t4 + 4][rb + 8]);
                unsigned al0 = __float_as_uint(AsLo[ks + t4][rb]);
                unsigned al1 = __float_as_uint(AsLo[ks + t4][rb + 8]);
                unsigned al2 = __float_as_uint(AsLo[ks + t4 + 4][rb]);
                unsigned al3 = __float_as_uint(AsLo[ks + t4 + 4][rb + 8]);
#pragma unroll
                for (int nt = 0; nt < 4; nt++) {
                    MMA_TF32(acc[mt][nt], al0, al1, al2, al3, bh[nt][0], bh[nt][1]);
                    MMA_TF32(acc[mt][nt], ah0, ah1, ah2, ah3, bl[nt][0], bl[nt][1]);
                    MMA_TF32(acc[mt][nt], ah0, ah1, ah2, ah3, bh[nt][0], bh[nt][1]);
                }
            }
        }
    };

    LOADAB(0);
    STOREAB();
    __syncthreads();
    for (int k0 = BKK; k0 < Kk; k0 += BKK) {
        LOADAB(k0);          // register prefetch overlaps compute
        COMPUTE();
        __syncthreads();
        STOREAB();
        __syncthreads();
    }
    COMPUTE();

    // ---- normal (row-major) writes ----
#pragma unroll
    for (int mt = 0; mt < 4; mt++) {
#pragma unroll
        for (int nt = 0; nt < 4; nt++) {
            int r0 = m0 + wm + 16*mt + g;
            int c0 = n0 + wn + 8*nt + 2*t4;
#pragma unroll
            for (int e = 0; e < 4; e++) {
                int row = r0 + (e >> 1) * 8;
                int col = c0 + (e & 1);
                float v = acc[mt][nt][e];
                if (EP == 1) v = -((sq[row] + sq[col]) - 2.f * v);
                C[(size_t)row * ldc + col] = v;
            }
        }
    }

    // ---- mirror writes, coalesced via smem staging (SYM off-diagonal only) ----
    if (SYM && bx != by) {
        float* Sst = smemS;     // 32x132 staging fits easily
#pragma unroll
        for (int p = 0; p < 4; p++) {
            __syncthreads();
            if ((wn >> 5) == p) {
#pragma unroll
                for (int mt = 0; mt < 4; mt++) {
#pragma unroll
                    for (int nt = 0; nt < 4; nt++) {
                        int rl0 = wm + 16*mt + g;
                        int cl0 = ((wn + 8*nt + 2*t4) & 31);
#pragma unroll
                        for (int e = 0; e < 4; e++) {
                            int rl = rl0 + (e >> 1) * 8;
                            int cl = cl0 + (e & 1);
                            float v = acc[mt][nt][e];
                            if (EP == 1)
                                v = -((sq[m0 + rl] + sq[n0 + p*32 + cl]) - 2.f * v);
                            Sst[cl*132 + rl] = v;
                        }
                    }
                }
            }
            __syncthreads();
            for (int q = tid; q < 32*128; q += 256) {
                int rm = q >> 7, cm = q & 127;
                C[(size_t)(n0 + p*32 + rm) * ldc + (m0 + cm)] = Sst[rm*132 + cm];
            }
        }
    }
}

// ---------------- SIMT SGEMM (64x64 tile; proven) for W_o + MLP ----------------
template<bool TB, int EP, int TBM, int TBN, int TMI, int TNI>
__launch_bounds__(256, 2)
__global__ void sgemm2(const float* __restrict__ A0, const float* __restrict__ B0,
                       float* __restrict__ C0, const float* __restrict__ bias0,
                       const float* __restrict__ A1, const float* __restrict__ B1,
                       float* __restrict__ C1, const float* __restrict__ bias1,
                       int M, int Nn, int Kk, int lda, int ldb, int ldc)
{
    static_assert((TBM/TMI)*(TBN/TNI) == 256, "thread count");
    const float* A    = blockIdx.z ? A1 : A0;
    const float* B    = blockIdx.z ? B1 : B0;
    float*       C    = blockIdx.z ? C1 : C0;
    const float* bias = blockIdx.z ? bias1 : bias0;

    __shared__ float As[2][BKK][TBM+4];
    __shared__ float Bs[2][BKK][TBN+4];
    const int tid = threadIdx.x;
    const int m0 = blockIdx.y * TBM, n0 = blockIdx.x * TBN;
    const int tm = (tid / (TBN/TNI)) * TMI;
    const int tn = (tid % (TBN/TNI)) * TNI;

    const int AIT = TBM*BKK/4/256 > 0 ? TBM*BKK/4/256 : 1;
    const int BIT = TBN*BKK/4/256 > 0 ? TBN*BKK/4/256 : 1;
    float4 ra[AIT], rb[BIT];

    auto LOADA = [&](int k0) {
#pragma unroll
        for (int it = 0; it < AIT; it++) {
            int q = tid + it*256;
            int r = q >> 2, c4 = (q & 3) * 4;
            ra[it] = *(const float4*)(A + (size_t)(m0 + r)*lda + k0 + c4);
        }
    };
    auto STOREA = [&](int buf) {
#pragma unroll
        for (int it = 0; it < AIT; it++) {
            int q = tid + it*256;
            int r = q >> 2, c4 = (q & 3) * 4;
            As[buf][c4+0][r] = ra[it].x; As[buf][c4+1][r] = ra[it].y;
            As[buf][c4+2][r] = ra[it].z; As[buf][c4+3][r] = ra[it].w;
        }
    };
    auto LOADB = [&](int k0) {
#pragma unroll
        for (int it = 0; it < BIT; it++) {
            int q = tid + it*256;
            if (!TB) {
                int r = q / (TBN/4), cn = (q % (TBN/4)) * 4;
                rb[it] = *(const float4*)(B + (size_t)(k0 + r)*ldb + n0 + cn);
            } else {
                int r = q >> 2, c4 = (q & 3) * 4;
                rb[it] = *(const float4*)(B + (size_t)(n0 + r)*ldb + k0 + c4);
            }
        }
    };
    auto STOREB = [&](int buf) {
#pragma unroll
        for (int it = 0; it < BIT; it++) {
            int q = tid + it*256;
            if (!TB) {
                int r = q / (TBN/4), cn = (q % (TBN/4)) * 4;
                Bs[buf][r][cn+0] = rb[it].x; Bs[buf][r][cn+1] = rb[it].y;
                Bs[buf][r][cn+2] = rb[it].z; Bs[buf][r][cn+3] = rb[it].w;
            } else {
                int r = q >> 2, c4 = (q & 3) * 4;
                Bs[buf][c4+0][r] = rb[it].x; Bs[buf][c4+1][r] = rb[it].y;
                Bs[buf][c4+2][r] = rb[it].z; Bs[buf][c4+3][r] = rb[it].w;
            }
        }
    };

    float acc[TMI][TNI];
#pragma unroll
    for (int i = 0; i < TMI; i++)
#pragma unroll
        for (int j = 0; j < TNI; j++) acc[i][j] = 0.f;

    auto COMPUTE = [&](int buf) {
#pragma unroll
        for (int k = 0; k < BKK; k++) {
            float a[TMI], b[TNI];
#pragma unroll
            for (int u = 0; u < TMI/4; u++) {
                float4 v = *(const float4*)&As[buf][k][tm + u*4];
                a[u*4+0] = v.x; a[u*4+1] = v.y; a[u*4+2] = v.z; a[u*4+3] = v.w;
            }
#pragma unroll
            for (int u = 0; u < TNI/4; u++) {
                float4 v = *(const float4*)&Bs[buf][k][tn + u*4];
                b[u*4+0] = v.x; b[u*4+1] = v.y; b[u*4+2] = v.z; b[u*4+3] = v.w;
            }
#pragma unroll
            for (int i = 0; i < TMI; i++)
#pragma unroll
                for (int j = 0; j < TNI; j++) acc[i][j] = fmaf(a[i], b[j], acc[i][j]);
        }
    };

    LOADA(0); LOADB(0);
    STOREA(0); STOREB(0);
    __syncthreads();
    int buf = 0;
    for (int k0 = BKK; k0 < Kk; k0 += BKK) {
        LOADA(k0); LOADB(k0);
        COMPUTE(buf);
        STOREA(buf ^ 1); STOREB(buf ^ 1);
        __syncthreads();
        buf ^= 1;
    }
    COMPUTE(buf);

#pragma unroll
    for (int i = 0; i < TMI; i++) {
        int row = m0 + tm + i;
#pragma unroll
        for (int j = 0; j < TNI; j++) {
            int col = n0 + tn + j;
            float v = acc[i][j];
            if (EP == 2) { v += bias[col]; v = fmaxf(v, 0.f); }
            C[(size_t)row * ldc + col] = v;
        }
    }
}

// ---------------- prep: z=0 rowsum-sq(user) -> sqU ; z=1 normalize(food) -> XnF ----------------
__global__ void prep_kernel(const float* __restrict__ user, float* __restrict__ sqU,
                            const float* __restrict__ food, float* __restrict__ XnF)
{
    const float* X = blockIdx.z ? food : user;
    int i = blockIdx.x, tid = threadIdx.x;
    float s = 0.f;
    for (int j = tid; j < DIN; j += 256) { float v = X[(size_t)i*DIN + j]; s = fmaf(v, v, s); }
    __shared__ float r[256];
    r[tid] = s; __syncthreads();
    for (int st = 128; st > 0; st >>= 1) { if (tid < st) r[tid] += r[tid + st]; __syncthreads(); }
    if (blockIdx.z == 0) {
        if (tid == 0) sqU[i] = r[0];
    } else {
        float nrm = sqrtf(r[0]);
        for (int j = tid; j < DIN; j += 256) XnF[(size_t)i*DIN + j] = X[(size_t)i*DIN + j] / nrm;
    }
}

// ---------------- tf32 split: z in {user, food, XnF} ----------------
__global__ void split3_kernel(const float* __restrict__ u, float* __restrict__ uh, float* __restrict__ ul,
                              const float* __restrict__ f, float* __restrict__ fh, float* __restrict__ fl,
                              const float* __restrict__ x, float* __restrict__ xh, float* __restrict__ xl)
{
    const float* in = blockIdx.z == 0 ? u : (blockIdx.z == 1 ? f : x);
    float* oh = blockIdx.z == 0 ? uh : (blockIdx.z == 1 ? fh : xh);
    float* ol = blockIdx.z == 0 ? ul : (blockIdx.z == 1 ? fl : xl);
    int i = blockIdx.x * blockDim.x + threadIdx.x;   // float4 index
    float4 v = ((const float4*)in)[i];
    float4 h, l;
    h.x = tf32r(v.x); l.x = tf32r(v.x - h.x);
    h.y = tf32r(v.y); l.y = tf32r(v.y - h.y);
    h.z = tf32r(v.z); l.z = tf32r(v.z - h.z);
    h.w = tf32r(v.w); l.w = tf32r(v.w - h.w);
    ((float4*)oh)[i] = h;
    ((float4*)ol)[i] = l;
}

// ---------------- deterministic total order: (value desc, index asc) ----------------
__device__ __forceinline__ bool better(float a, int ai, float b, int bi)
{
    return (a > b) || (a == b && ai < bi);
}

// ---------------- single-pass top-6, 256 threads, z-batched (PROVEN) ----------------
__global__ void top6_onepass(const float* __restrict__ S0, const float* __restrict__ S1,
                             int* __restrict__ oI0, float* __restrict__ oV0,
                             int* __restrict__ oI1, float* __restrict__ oV1)
{
    const float* S = blockIdx.z ? S1 : S0;
    int*   oI = blockIdx.z ? oI1 : oI0;
    float* oV = blockIdx.z ? oV1 : oV0;

    __shared__ float sv[256*TOPK];
    __shared__ int   si[256*TOPK];
    __shared__ int   ch[TOPK];
    __shared__ float rv[256];
    __shared__ int   ri[256];

    int row = blockIdx.x, tid = threadIdx.x;
    const float* Sr = S + (size_t)row * NN;

    float lv[TOPK]; int li[TOPK];
#pragma unroll
    for (int t = 0; t < TOPK; t++) { lv[t] = -FLT_MAX; li[t] = 0x7FFFFFFF; }
    for (int j = tid; j < NN; j += 256) {
        float x = Sr[j];
        if (better(x, j, lv[TOPK-1], li[TOPK-1])) {
            lv[TOPK-1] = x; li[TOPK-1] = j;
#pragma unroll
            for (int t = TOPK-1; t > 0; t--) {
                if (better(lv[t], li[t], lv[t-1], li[t-1])) {
                    float tv = lv[t]; lv[t] = lv[t-1]; lv[t-1] = tv;
                    int ti = li[t]; li[t] = li[t-1]; li[t-1] = ti;
                } else break;
            }
        }
    }
#pragma unroll
    for (int t = 0; t < TOPK; t++) { sv[tid*TOPK+t] = lv[t]; si[tid*TOPK+t] = li[t]; }
    __syncthreads();

    for (int t = 0; t < TOPK; t++) {
        float bv = -FLT_MAX; int bi = 0x7FFFFFFF;
#pragma unroll
        for (int u = 0; u < TOPK; u++) {
            int e = tid*TOPK + u;
            int cidx = si[e];
            bool used = false;
            for (int w = 0; w < t; w++) used |= (ch[w] == cidx);
            if (!used && better(sv[e], cidx, bv, bi)) { bv = sv[e]; bi = cidx; }
        }
        rv[tid] = bv; ri[tid] = bi;
        __syncthreads();
        if (tid < 32) {
#pragma unroll
            for (int o = 32; o < 256; o += 32) {
                if (better(rv[tid+o], ri[tid+o], bv, bi)) { bv = rv[tid+o]; bi = ri[tid+o]; }
            }
#pragma unroll
            for (int o = 16; o > 0; o >>= 1) {
                float ov = __shfl_down_sync(0xFFFFFFFFu, bv, o);
                int   oi = __shfl_down_sync(0xFFFFFFFFu, bi, o);
                if (better(ov, oi, bv, bi)) { bv = ov; bi = oi; }
            }
            if (tid == 0) {
                ch[t] = bi;
                oI[row*TOPK + t] = bi;
                oV[row*TOPK + t] = bv;
            }
        }
        __syncthreads();
    }
}

// ---------------- adjacency mask build, z-batched (PROVEN) ----------------
__global__ void clear_masks()
{
    int i = blockIdx.x * blockDim.x + threadIdx.x;
    ((unsigned int*)g_maskU)[i] = 0u;
    ((unsigned int*)g_maskF)[i] = 0u;
}

__global__ void mark_kernel2(const int* __restrict__ idx0, const float* __restrict__ val0,
                             unsigned char* __restrict__ mask0,
                             const int* __restrict__ idx1, const float* __restrict__ val1,
                             unsigned char* __restrict__ mask1)
{
    const int*   idx  = blockIdx.z ? idx1 : idx0;
    const float* val  = blockIdx.z ? val1 : val0;
    unsigned char* mask = blockIdx.z ? mask1 : mask0;
    int needPos = blockIdx.z;
    int i = blockIdx.x * blockDim.x + threadIdx.x;
    if (i >= NN) return;
#pragma unroll
    for (int t = 0; t < TOPK; t++) {
        int j = idx[i*TOPK + t];
        if (j == i) continue;
        if (needPos && !(val[i*TOPK + t] > 0.f)) continue;
        mask[(size_t)i*NN + j] = 1;
        mask[(size_t)j*NN + i] = 1;
    }
}

__global__ void collect_kernel2(const unsigned char* __restrict__ mask0,
                                int* __restrict__ nbr0, int* __restrict__ cnt0,
                                const unsigned char* __restrict__ mask1,
                                int* __restrict__ nbr1, int* __restrict__ cnt1)
{
    const unsigned char* mask = blockIdx.z ? mask1 : mask0;
    int* nbr = blockIdx.z ? nbr1 : nbr0;
    int* cnt = blockIdx.z ? cnt1 : cnt0;
    int warp = (blockIdx.x * blockDim.x + threadIdx.x) >> 5;
    int lane = threadIdx.x & 31;
    if (warp >= NN) return;
    const unsigned char* mr = mask + (size_t)warp * NN;
    int c = 0;
    for (int base = 0; base < NN; base += 32) {
        bool m = mr[base + lane] != 0;
        unsigned b = __ballot_sync(0xFFFFFFFFu, m);
        if (m) nbr[(size_t)warp*MAXD + c + __popc(b & ((1u << lane) - 1u))] = base + lane;
        c += __popc(b);
    }
    if (lane == 0) cnt[warp] = c;
}

// ---------------- sparse attention + aggregate + elu (hub-safe, PROVEN), z-batched ----------------
__global__ void att_agg2(const float* __restrict__ Wh0, const float* __restrict__ s10,
                         const float* __restrict__ s20, const int* __restrict__ nbr0,
                         const int* __restrict__ cnt0, float* __restrict__ out0,
                         const float* __restrict__ Wh1, const float* __restrict__ s11,
                         const float* __restrict__ s21, const int* __restrict__ nbr1,
                         const int* __restrict__ cnt1, float* __restrict__ out1,
                         int rowStride, int nheads)
{
    const float* Wh = blockIdx.z ? Wh1 : Wh0;
    const float* s1 = blockIdx.z ? s11 : s10;
    const float* s2 = blockIdx.z ? s21 : s20;
    const int* nbr  = blockIdx.z ? nbr1 : nbr0;
    const int* cnt  = blockIdx.z ? cnt1 : cnt0;
    float* out      = blockIdx.z ? out1 : out0;

    __shared__ int   sidx[MAXD];
    __shared__ float sw[NH][MAXD];
    __shared__ float hs[NH];
    int i = blockIdx.x, tid = threadIdx.x;
    int wid = tid >> 5, lane = tid & 31;
    int c = cnt[i];

    for (int t = tid; t < c; t += 256) sidx[t] = nbr[(size_t)i*MAXD + t];
    __syncthreads();

    for (int q = tid; q < nheads*c; q += 256) {
        int h = q / c, t = q - h*c;
        float e = s1[h*NN + i] + s2[h*NN + sidx[t]];
        sw[h][t] = (e >= 0.f) ? e : 0.2f * e;
    }
    __syncthreads();

    if (wid < nheads) {
        int h = wid;
        float m = -FLT_MAX;
        for (int t = lane; t < c; t += 32) m = fmaxf(m, sw[h][t]);
#pragma unroll
        for (int o = 16; o > 0; o >>= 1) m = fmaxf(m, __shfl_xor_sync(0xFFFFFFFFu, m, o));
        float s = 0.f;
        for (int t = lane; t < c; t += 32) { float ex = expf(sw[h][t] - m); sw[h][t] = ex; s += ex; }
#pragma unroll
        for (int o = 16; o > 0; o >>= 1) s += __shfl_xor_sync(0xFFFFFFFFu, s, o);
        if (lane == 0) hs[h] = s;
    }
    __syncthreads();

    for (int q = tid; q < nheads*c; q += 256) {
        int h = q / c, t = q - h*c;
        sw[h][t] /= hs[h];
    }
    __syncthreads();

    for (int h = 0; h < nheads; h++) {
        float acc = 0.f;
#pragma unroll 4
        for (int t = 0; t < c; t++)
            acc = fmaf(sw[h][t], Wh[(size_t)sidx[t]*rowStride + h*HID + tid], acc);
        out[(size_t)i*rowStride + h*HID + tid] = (acc > 0.f) ? acc : expm1f(acc);
    }
}

// ---------------- repack W + tf32 split, z-batched ----------------
__global__ void repack_W2(const float* __restrict__ W0, float* __restrict__ Whi0,
                          float* __restrict__ Wlo0,
                          const float* __restrict__ W1, float* __restrict__ Whi1,
                          float* __restrict__ Wlo1)
{
    const float* W = blockIdx.z ? W1 : W0;
    float* Whi = blockIdx.z ? Whi1 : Whi0;
    float* Wlo = blockIdx.z ? Wlo1 : Wlo0;
    int i = blockIdx.x * blockDim.x + threadIdx.x;
    if (i >= DIN*NH*HID) return;
    int d = i / (NH*HID);
    int r = i % (NH*HID);
    int h = r / HID;
    int f = r % HID;
    float v = W[(size_t)h*DIN*HID + (size_t)d*HID + f];
    float hi = tf32r(v);
    Whi[i] = hi;
    Wlo[i] = tf32r(v - hi);
}

__global__ void s1s2_kernel2(const float* __restrict__ WhA, const float* __restrict__ aA,
                             float* __restrict__ s1A, float* __restrict__ s2A,
                             const float* __restrict__ WhB, const float* __restrict__ aB,
                             float* __restrict__ s1B, float* __restrict__ s2B,
                             int rowStride)
{
    const float* Wh = blockIdx.z ? WhB : WhA;
    const float* a  = blockIdx.z ? aB : aA;
    float* s1 = blockIdx.z ? s1B : s1A;
    float* s2 = blockIdx.z ? s2B : s2A;
    int i = blockIdx.x, h = blockIdx.y, f = threadIdx.x;
    float w = Wh[(size_t)i*rowStride + h*HID + f];
    float v1 = w * a[h*2*HID + f];
    float v2 = w * a[h*2*HID + HID + f];
    __shared__ float r1[256], r2[256];
    r1[f] = v1; r2[f] = v2; __syncthreads();
    for (int st = 128; st > 0; st >>= 1) {
        if (f < st) { r1[f] += r1[f+st]; r2[f] += r2[f+st]; }
        __syncthreads();
    }
    if (f == 0) { s1[h*NN + i] = r1[0]; s2[h*NN + i] = r2[0]; }
}

// ---------------- MLP pieces (PROVEN) ----------------
__global__ void concat_kernel()
{
    int i = blockIdx.x, c = threadIdx.x;
    g_pair[(size_t)i*512 + c] = (c < HID) ? g_embU[(size_t)i*HID + c]
                                          : g_embF[(size_t)i*HID + (c - HID)];
}

__global__ void mlp_final_kernel(const float* __restrict__ act, const float* __restrict__ W,
                                 const float* __restrict__ b, float* __restrict__ out)
{
    int i = blockIdx.x, tid = threadIdx.x;
    float v = act[(size_t)i*128 + tid] * W[tid];
    __shared__ float r[128];
    r[tid] = v; __syncthreads();
    for (int st = 64; st > 0; st >>= 1) { if (tid < st) r[tid] += r[tid+st]; __syncthreads(); }
    if (tid == 0) out[i] = r[0] + b[0];
}

// ---------------- host launch ----------------
template <typename T>
static T* sym(const void* s)
{
    void* p = nullptr;
    cudaGetSymbolAddress(&p, s);
    return (T*)p;
}

extern "C" void kernel_launch(void* const* d_in, const int* in_sizes, int n_in,
                              void* d_out, int out_size)
{
    const float* user_nodes = (const float*)d_in[0];
    const float* food_nodes = (const float*)d_in[1];
    const float* user_W_h   = (const float*)d_in[2];
    const float* user_a_h   = (const float*)d_in[3];
    const float* user_W_o   = (const float*)d_in[4];
    const float* user_a_o   = (const float*)d_in[5];
    const float* food_W_h   = (const float*)d_in[6];
    const float* food_a_h   = (const float*)d_in[7];
    const float* food_W_o   = (const float*)d_in[8];
    const float* food_a_o   = (const float*)d_in[9];
    const float* mlp_W0 = (const float*)d_in[10];
    const float* mlp_b0 = (const float*)d_in[11];
    const float* mlp_W1 = (const float*)d_in[12];
    const float* mlp_b1 = (const float*)d_in[13];
    const float* mlp_W2 = (const float*)d_in[14];
    const float* mlp_b2 = (const float*)d_in[15];
    const float* mlp_W3 = (const float*)d_in[16];
    const float* mlp_b3 = (const float*)d_in[17];
    float* out = (float*)d_out;

    float* pZero  = sym<float>(g_zero);
    float* pSqU   = sym<float>(g_sqU);
    float* pXnF   = sym<float>(g_XnF);
    float* pSimU  = sym<float>(g_simU);
    float* pSimF  = sym<float>(g_simF);
    int*   pTidxU = sym<int>(g_tidxU);
    float* pTvalU = sym<float>(g_tvalU);
    int*   pTidxF = sym<int>(g_tidxF);
    float* pTvalF = sym<float>(g_tvalF);
    unsigned char* pMaskU = sym<unsigned char>(g_maskU);
    unsigned char* pMaskF = sym<unsigned char>(g_maskF);
    int*   pNbrU = sym<int>(g_nbrU);
    int*   pCntU = sym<int>(g_cntU);
    int*   pNbrF = sym<int>(g_nbrF);
    int*   pCntF = sym<int>(g_cntF);
    float* pUhi = sym<float>(g_uhi);  float* pUlo = sym<float>(g_ulo);
    float* pFhi = sym<float>(g_fhi);  float* pFlo = sym<float>(g_flo);
    float* pXhi = sym<float>(g_xhi);  float* pXlo = sym<float>(g_xlo);
    float* pWhiU = sym<float>(g_WhiU); float* pWloU = sym<float>(g_WloU);
    float* pWhiF = sym<float>(g_WhiF); float* pWloF = sym<float>(g_WloF);
    float* pWhU  = sym<float>(g_WhU);
    float* pWhF  = sym<float>(g_WhF);
    float* pS1U  = sym<float>(g_s1U);
    float* pS2U  = sym<float>(g_s2U);
    float* pS1F  = sym<float>(g_s1F);
    float* pS2F  = sym<float>(g_s2F);
    float* pHidU = sym<float>(g_hidU);
    float* pHidF = sym<float>(g_hidF);
    float* pWhoU = sym<float>(g_WhoU);
    float* pWhoF = sym<float>(g_WhoF);
    float* pS1oU = sym<float>(g_s1oU);
    float* pS2oU = sym<float>(g_s2oU);
    float* pS1oF = sym<float>(g_s1oF);
    float* pS2oF = sym<float>(g_s2oF);
    float* pEmbU = sym<float>(g_embU);
    float* pEmbF = sym<float>(g_embF);
    float* pPair = sym<float>(g_pair);
    float* pAct0 = sym<float>(g_act0);
    float* pAct1 = sym<float>(g_act1);
    float* pAct2 = sym<float>(g_act2);

    const int NTRI = (NN/128) * (NN/128 + 1) / 2;   // 136 upper-tri tiles

    // ---- graph build ----
    prep_kernel<<<dim3(NN,1,2), 256>>>(user_nodes, pSqU, food_nodes, pXnF);
    split3_kernel<<<dim3(NN*DIN/4/256,1,3), 256>>>(user_nodes, pUhi, pUlo,
                                                   food_nodes, pFhi, pFlo,
                                                   pXnF, pXhi, pXlo);
    // batched sims on tensor cores: z=0 user euclid (-d^2), z=1 food cosine x2 (sq=0)
    mma_gemm2<true, 1, true><<<dim3(NTRI,1,2), 256>>>(
        pUhi, pUlo, pUhi, pUlo, pSimU, pSqU,
        pXhi, pXlo, pXhi, pXlo, pSimF, pZero,
        NN, NN, DIN, DIN, DIN, NN);
    top6_onepass<<<dim3(NN,1,2), 256>>>(pSimU, pSimF, pTidxU, pTvalU, pTidxF, pTvalF);

    clear_masks<<<(NN*NN/4)/256, 256>>>();
    mark_kernel2<<<dim3((NN+255)/256,1,2), 256>>>(pTidxU, pTvalU, pMaskU,
                                                  pTidxF, pTvalF, pMaskF);
    collect_kernel2<<<dim3(NN*32/256,1,2), 256>>>(pMaskU, pNbrU, pCntU,
                                                  pMaskF, pNbrF, pCntF);

    // ---- GAT hidden layer (user & food batched) ----
    repack_W2<<<dim3((DIN*NH*HID+255)/256,1,2), 256>>>(user_W_h, pWhiU, pWloU,
                                                       food_W_h, pWhiF, pWloF);
    mma_gemm2<false, 0, false><<<dim3((NH*HID)/128, NN/128, 2), 256>>>(
        pUhi, pUlo, pWhiU, pWloU, pWhU, nullptr,
        pFhi, pFlo, pWhiF, pWloF, pWhF, nullptr,
        NN, NH*HID, DIN, DIN, NH*HID, NH*HID);
    s1s2_kernel2<<<dim3(NN, NH, 2), 256>>>(pWhU, user_a_h, pS1U, pS2U,
                                           pWhF, food_a_h, pS1F, pS2F, NH*HID);
    att_agg2<<<dim3(NN,1,2), 256>>>(pWhU, pS1U, pS2U, pNbrU, pCntU, pHidU,
                                    pWhF, pS1F, pS2F, pNbrF, pCntF, pHidF,
                                    NH*HID, NH);

    // ---- GAT output layer (user & food batched; SIMT) ----
    sgemm2<false, 0, 64,64,4,4><<<dim3(HID/64, NN/64, 2), 256>>>(
        pHidU, user_W_o, pWhoU, nullptr,
        pHidF, food_W_o, pWhoF, nullptr,
        NN, HID, NH*HID, NH*HID, HID, HID);
    s1s2_kernel2<<<dim3(NN, 1, 2), 256>>>(pWhoU, user_a_o, pS1oU, pS2oU,
                                          pWhoF, food_a_o, pS1oF, pS2oF, HID);
    att_agg2<<<dim3(NN,1,2), 256>>>(pWhoU, pS1oU, pS2oU, pNbrU, pCntU, pEmbU,
                                    pWhoF, pS1oF, pS2oF, pNbrF, pCntF, pEmbF,
                                    HID, 1);

    // ---- MLP (SIMT) ----
    concat_kernel<<<NN, 512>>>();
    sgemm2<false, 2, 64,64,4,4><<<dim3(512/64, NN/64, 1), 256>>>(
        pPair, mlp_W0, pAct0, mlp_b0,
        pPair, mlp_W0, pAct0, mlp_b0,
        NN, 512, 512, 512, 512, 512);
    sgemm2<false, 2, 64,64,4,4><<<dim3(256/64, NN/64, 1), 256>>>(
        pAct0, mlp_W1, pAct1, mlp_b1,
        pAct0, mlp_W1, pAct1, mlp_b1,
        NN, 256, 512, 512, 256, 256);
    sgemm2<false, 2, 64,64,4,4><<<dim3(128/64, NN/64, 1), 256>>>(
        pAct1, mlp_W2, pAct2, mlp_b2,
        pAct1, mlp_W2, pAct2, mlp_b2,
        NN, 128, 256, 256, 128, 128);
    mlp_final_kernel<<<NN, 128>>>(pAct2, mlp_W3, mlp_b3, out);
}

// round 14
// speedup vs baseline: 1.0714x; 1.0714x over previous
#include <cuda_runtime.h>
#include <math.h>
#include <float.h>

// ---------------- problem constants ----------------
#define NN   2048
#define DIN  512
#define HID  256
#define NH   4
#define TOPK 6      // k+1
#define MAXD 2048   // no truncation (kNN hubness gives in-degrees in the hundreds)
#define BKK  16     // SIMT sgemm slab
#define KSLAB 8     // mma slab

// ---------------- device scratch (static, no allocs; zero-initialized) ----------------
__device__ float g_zero[NN];       // stays all-zero
__device__ float g_sqU[NN];
__device__ float g_XnF[NN*DIN];
__device__ float g_simU[NN*NN];
__device__ float g_simF[NN*NN];
__device__ int   g_tidxU[NN*TOPK];
__device__ float g_tvalU[NN*TOPK];
__device__ int   g_tidxF[NN*TOPK];
__device__ float g_tvalF[NN*TOPK];
__device__ unsigned char g_maskU[NN*NN];
__device__ unsigned char g_maskF[NN*NN];
__device__ int   g_nbrU[NN*MAXD];
__device__ int   g_cntU[NN];
__device__ int   g_nbrF[NN*MAXD];
__device__ int   g_cntF[NN];
// tf32 split buffers
__device__ float g_uhi[NN*DIN];
__device__ float g_ulo[NN*DIN];
__device__ float g_fhi[NN*DIN];
__device__ float g_flo[NN*DIN];
__device__ float g_xhi[NN*DIN];
__device__ float g_xlo[NN*DIN];
__device__ float g_WhiU[DIN*NH*HID];
__device__ float g_WloU[DIN*NH*HID];
__device__ float g_WhiF[DIN*NH*HID];
__device__ float g_WloF[DIN*NH*HID];
__device__ float g_WhU[NN*NH*HID];
__device__ float g_WhF[NN*NH*HID];
__device__ float g_s1U[NH*NN];
__device__ float g_s2U[NH*NN];
__device__ float g_s1F[NH*NN];
__device__ float g_s2F[NH*NN];
__device__ float g_hidU[NN*NH*HID];
__device__ float g_hidF[NN*NH*HID];
__device__ float g_WhoU[NN*HID];
__device__ float g_WhoF[NN*HID];
__device__ float g_s1oU[NN];
__device__ float g_s2oU[NN];
__device__ float g_s1oF[NN];
__device__ float g_s2oF[NN];
__device__ float g_embU[NN*HID];
__device__ float g_embF[NN*HID];
__device__ float g_pair[NN*512];
__device__ float g_act0[NN*512];
__device__ float g_act1[NN*256];
__device__ float g_act2[NN*128];

__device__ __forceinline__ float tf32r(float x)
{
    float y;
    asm("cvt.rna.tf32.f32 %0, %1;" : "=f"(y) : "f"(x));
    return y;
}

#define MMA_TF32(c, a0, a1, a2, a3, b0, b1) \
    asm volatile("mma.sync.aligned.m16n8k8.row.col.f32.tf32.tf32.f32 " \
                 "{%0,%1,%2,%3}, {%4,%5,%6,%7}, {%8,%9}, {%0,%1,%2,%3};" \
                 : "+f"(c[0]), "+f"(c[1]), "+f"(c[2]), "+f"(c[3]) \
                 : "r"(a0), "r"(a1), "r"(a2), "r"(a3), "r"(b0), "r"(b1))

// smem layout (floats) for mma kernel, per stage:
//   A-hi frag: [8 mb][32 lane][4]           = 1024
//   A-lo frag: +1024                         = 1024
//   B-hi frag: [16 nb][66] (lane*2+sel, pad) = 1056
//   B-lo frag: +1056                         = 1056
#define OFF_AL 1024
#define OFF_BH 2048
#define OFF_BL 3104
#define STAGE  4160

// ---------------- tensor-core GEMM: 3xTF32, fragment-major smem, double-buffered ----------------
// Same arithmetic order as the R13 kernel (validated: rel_err 4.2e-6).
// TB=false: C = A[M,K]*B[K,Nn]; TB=true: C = A[M,K]*B[Nn,K]^T
// EP: 0 none; 1 negd2; SYM: upper-tri + coalesced mirror.
template<bool TB, int EP, bool SYM>
__launch_bounds__(256)
__global__ void mma_gemm2(const float* __restrict__ Ah0, const float* __restrict__ Al0,
                          const float* __restrict__ Bh0, const float* __restrict__ Bl0,
                          float* __restrict__ C0, const float* __restrict__ sq0,
                          const float* __restrict__ Ah1, const float* __restrict__ Al1,
                          const float* __restrict__ Bh1, const float* __restrict__ Bl1,
                          float* __restrict__ C1, const float* __restrict__ sq1,
                          int M, int Nn, int Kk, int lda, int ldb, int ldc)
{
    const float* Ah = blockIdx.z ? Ah1 : Ah0;
    const float* Al = blockIdx.z ? Al1 : Al0;
    const float* Bh = blockIdx.z ? Bh1 : Bh0;
    const float* Bl = blockIdx.z ? Bl1 : Bl0;
    float*       C  = blockIdx.z ? C1 : C0;
    const float* sq = blockIdx.z ? sq1 : sq0;

    __shared__ float smemS[2*STAGE];    // 33280 B

    const int tid = threadIdx.x;
    const int wid = tid >> 5, lane = tid & 31;
    const int g = lane >> 2, t4 = lane & 3;
    const int wmb = (wid >> 2) * 4;     // m16-block base within tile (0 or 4)
    const int wnb = (wid & 3) * 4;      // n8-block base (0,4,8,12)
    const int wm = (wid >> 2) * 64;
    const int wn = (wid & 3) * 32;

    int bx = blockIdx.x, by = blockIdx.y;
    if (SYM) {
        int nb = M / 128;
        int idx = blockIdx.x, bi = 0;
        while (idx >= nb - bi) { idx -= nb - bi; bi++; }
        by = bi; bx = bi + idx;
    }
    const int m0 = by * 128, n0 = bx * 128;

    // A global-load + frag-store indices: thread covers (row ar, k ac4..ac4+3)
    const int ar  = tid >> 1;
    const int ac4 = (tid & 1) * 4;
    const int abase = (ar >> 4)*128 + (ar & 7)*16 + (ac4 >> 2)*2 + ((ar >> 3) & 1);
    // B indices (both variants computed; template removes the unused one)
    const int br  = tid >> 1;            // TB=true: B row (n), k = bc4..+3
    const int bc4 = (tid & 1) * 4;
    const int bbaseT = (br >> 3)*66 + (br & 7)*8 + (bc4 >> 2);
    const int bk  = tid >> 5;            // TB=false: k-row, n = bcn..+3
    const int bcn = (tid & 31) * 4;
    const int bbaseF = (bcn >> 3)*66 + (bcn & 7)*8 + (bk & 3)*2 + (bk >> 2);

    float4 vah, vala, vbh, vbl;
    auto LOADAB = [&](int k0) {
        vah  = *(const float4*)(Ah + (size_t)(m0 + ar)*lda + k0 + ac4);
        vala = *(const float4*)(Al + (size_t)(m0 + ar)*lda + k0 + ac4);
        if (TB) {
            vbh = *(const float4*)(Bh + (size_t)(n0 + br)*ldb + k0 + bc4);
            vbl = *(const float4*)(Bl + (size_t)(n0 + br)*ldb + k0 + bc4);
        } else {
            vbh = *(const float4*)(Bh + (size_t)(k0 + bk)*ldb + n0 + bcn);
            vbl = *(const float4*)(Bl + (size_t)(k0 + bk)*ldb + n0 + bcn);
        }
    };
    auto STOREAB = [&](int s) {
        float* AH = smemS + s*STAGE;
        float* AL = AH + OFF_AL;
        float* BH = AH + OFF_BH;
        float* BL = AH + OFF_BL;
        AH[abase+0]  = vah.x;  AH[abase+4]  = vah.y;  AH[abase+8]  = vah.z;  AH[abase+12] = vah.w;
        AL[abase+0]  = vala.x; AL[abase+4]  = vala.y; AL[abase+8]  = vala.z; AL[abase+12] = vala.w;
        if (TB) {
            BH[bbaseT+0] = vbh.x; BH[bbaseT+2] = vbh.y; BH[bbaseT+4] = vbh.z; BH[bbaseT+6] = vbh.w;
            BL[bbaseT+0] = vbl.x; BL[bbaseT+2] = vbl.y; BL[bbaseT+4] = vbl.z; BL[bbaseT+6] = vbl.w;
        } else {
            BH[bbaseF+0]  = vbh.x; BH[bbaseF+8]  = vbh.y;
            BH[bbaseF+16] = vbh.z; BH[bbaseF+24] = vbh.w;
            BL[bbaseF+0]  = vbl.x; BL[bbaseF+8]  = vbl.y;
            BL[bbaseF+16] = vbl.z; BL[bbaseF+24] = vbl.w;
        }
    };

    float acc[4][4][4];
#pragma unroll
    for (int i = 0; i < 4; i++)
#pragma unroll
        for (int j = 0; j < 4; j++)
#pragma unroll
            for (int e = 0; e < 4; e++) acc[i][j][e] = 0.f;

    auto COMPUTE = [&](int s) {
        const float* base = smemS + s*STAGE;
        const float4* AH4 = (const float4*)base;
        const float4* AL4 = (const float4*)(base + OFF_AL);
        const float*  BHf = base + OFF_BH;
        const float*  BLf = base + OFF_BL;
        unsigned bh[4][2], bl[4][2];
#pragma unroll
        for (int nt = 0; nt < 4; nt++) {
            float2 h = *(const float2*)&BHf[(wnb + nt)*66 + lane*2];
            float2 l = *(const float2*)&BLf[(wnb + nt)*66 + lane*2];
            bh[nt][0] = __float_as_uint(h.x); bh[nt][1] = __float_as_uint(h.y);
            bl[nt][0] = __float_as_uint(l.x); bl[nt][1] = __float_as_uint(l.y);
        }
#pragma unroll
        for (int mt = 0; mt < 4; mt++) {
            float4 ha = AH4[(wmb + mt)*32 + lane];
            float4 la = AL4[(wmb + mt)*32 + lane];
            unsigned ah0 = __float_as_uint(ha.x), ah1 = __float_as_uint(ha.y);
            unsigned ah2 = __float_as_uint(ha.z), ah3 = __float_as_uint(ha.w);
            unsigned al0 = __float_as_uint(la.x), al1 = __float_as_uint(la.y);
            unsigned al2 = __float_as_uint(la.z), al3 = __float_as_uint(la.w);
#pragma unroll
            for (int nt = 0; nt < 4; nt++) {
                MMA_TF32(acc[mt][nt], al0, al1, al2, al3, bh[nt][0], bh[nt][1]);
                MMA_TF32(acc[mt][nt], ah0, ah1, ah2, ah3, bl[nt][0], bl[nt][1]);
                MMA_TF32(acc[mt][nt], ah0, ah1, ah2, ah3, bh[nt][0], bh[nt][1]);
            }
        }
    };

    LOADAB(0);
    STOREAB(0);
    __syncthreads();
    int s = 0;
    for (int k0 = KSLAB; k0 < Kk; k0 += KSLAB) {
        LOADAB(k0);          // register prefetch overlaps compute
        COMPUTE(s);
        STOREAB(s ^ 1);
        __syncthreads();
        s ^= 1;
    }
    COMPUTE(s);

    // ---- normal (row-major) writes ----
#pragma unroll
    for (int mt = 0; mt < 4; mt++) {
#pragma unroll
        for (int nt = 0; nt < 4; nt++) {
            int r0 = m0 + wm + 16*mt + g;
            int c0 = n0 + wn + 8*nt + 2*t4;
#pragma unroll
            for (int e = 0; e < 4; e++) {
                int row = r0 + (e >> 1) * 8;
                int col = c0 + (e & 1);
                float v = acc[mt][nt][e];
                if (EP == 1) v = -((sq[row] + sq[col]) - 2.f * v);
                C[(size_t)row * ldc + col] = v;
            }
        }
    }

    // ---- mirror writes, coalesced via smem staging (SYM off-diagonal only) ----
    if (SYM && bx != by) {
        float* Sst = smemS;     // 32x132 staging = 4224 floats, fits
#pragma unroll
        for (int p = 0; p < 4; p++) {
            __syncthreads();
            if ((wn >> 5) == p) {
#pragma unroll
                for (int mt = 0; mt < 4; mt++) {
#pragma unroll
                    for (int nt = 0; nt < 4; nt++) {
                        int rl0 = wm + 16*mt + g;
                        int cl0 = ((wn + 8*nt + 2*t4) & 31);
#pragma unroll
                        for (int e = 0; e < 4; e++) {
                            int rl = rl0 + (e >> 1) * 8;
                            int cl = cl0 + (e & 1);
                            float v = acc[mt][nt][e];
                            if (EP == 1)
                                v = -((sq[m0 + rl] + sq[n0 + p*32 + cl]) - 2.f * v);
                            Sst[cl*132 + rl] = v;
                        }
                    }
                }
            }
            __syncthreads();
            for (int q = tid; q < 32*128; q += 256) {
                int rm = q >> 7, cm = q & 127;
                C[(size_t)(n0 + p*32 + rm) * ldc + (m0 + cm)] = Sst[rm*132 + cm];
            }
        }
    }
}

// ---------------- SIMT SGEMM (64x64 tile; proven) for W_o + MLP ----------------
template<bool TB, int EP, int TBM, int TBN, int TMI, int TNI>
__launch_bounds__(256, 2)
__global__ void sgemm2(const float* __restrict__ A0, const float* __restrict__ B0,
                       float* __restrict__ C0, const float* __restrict__ bias0,
                       const float* __restrict__ A1, const float* __restrict__ B1,
                       float* __restrict__ C1, const float* __restrict__ bias1,
                       int M, int Nn, int Kk, int lda, int ldb, int ldc)
{
    static_assert((TBM/TMI)*(TBN/TNI) == 256, "thread count");
    const float* A    = blockIdx.z ? A1 : A0;
    const float* B    = blockIdx.z ? B1 : B0;
    float*       C    = blockIdx.z ? C1 : C0;
    const float* bias = blockIdx.z ? bias1 : bias0;

    __shared__ float As[2][BKK][TBM+4];
    __shared__ float Bs[2][BKK][TBN+4];
    const int tid = threadIdx.x;
    const int m0 = blockIdx.y * TBM, n0 = blockIdx.x * TBN;
    const int tm = (tid / (TBN/TNI)) * TMI;
    const int tn = (tid % (TBN/TNI)) * TNI;

    const int AIT = TBM*BKK/4/256 > 0 ? TBM*BKK/4/256 : 1;
    const int BIT = TBN*BKK/4/256 > 0 ? TBN*BKK/4/256 : 1;
    float4 ra[AIT], rb[BIT];

    auto LOADA = [&](int k0) {
#pragma unroll
        for (int it = 0; it < AIT; it++) {
            int q = tid + it*256;
            int r = q >> 2, c4 = (q & 3) * 4;
            ra[it] = *(const float4*)(A + (size_t)(m0 + r)*lda + k0 + c4);
        }
    };
    auto STOREA = [&](int buf) {
#pragma unroll
        for (int it = 0; it < AIT; it++) {
            int q = tid + it*256;
            int r = q >> 2, c4 = (q & 3) * 4;
            As[buf][c4+0][r] = ra[it].x; As[buf][c4+1][r] = ra[it].y;
            As[buf][c4+2][r] = ra[it].z; As[buf][c4+3][r] = ra[it].w;
        }
    };
    auto LOADB = [&](int k0) {
#pragma unroll
        for (int it = 0; it < BIT; it++) {
            int q = tid + it*256;
            if (!TB) {
                int r = q / (TBN/4), cn = (q % (TBN/4)) * 4;
                rb[it] = *(const float4*)(B + (size_t)(k0 + r)*ldb + n0 + cn);
            } else {
                int r = q >> 2, c4 = (q & 3) * 4;
                rb[it] = *(const float4*)(B + (size_t)(n0 + r)*ldb + k0 + c4);
            }
        }
    };
    auto STOREB = [&](int buf) {
#pragma unroll
        for (int it = 0; it < BIT; it++) {
            int q = tid + it*256;
            if (!TB) {
                int r = q / (TBN/4), cn = (q % (TBN/4)) * 4;
                Bs[buf][r][cn+0] = rb[it].x; Bs[buf][r][cn+1] = rb[it].y;
                Bs[buf][r][cn+2] = rb[it].z; Bs[buf][r][cn+3] = rb[it].w;
            } else {
                int r = q >> 2, c4 = (q & 3) * 4;
                Bs[buf][c4+0][r] = rb[it].x; Bs[buf][c4+1][r] = rb[it].y;
                Bs[buf][c4+2][r] = rb[it].z; Bs[buf][c4+3][r] = rb[it].w;
            }
        }
    };

    float acc[TMI][TNI];
#pragma unroll
    for (int i = 0; i < TMI; i++)
#pragma unroll
        for (int j = 0; j < TNI; j++) acc[i][j] = 0.f;

    auto COMPUTE = [&](int buf) {
#pragma unroll
        for (int k = 0; k < BKK; k++) {
            float a[TMI], b[TNI];
#pragma unroll
            for (int u = 0; u < TMI/4; u++) {
                float4 v = *(const float4*)&As[buf][k][tm + u*4];
                a[u*4+0] = v.x; a[u*4+1] = v.y; a[u*4+2] = v.z; a[u*4+3] = v.w;
            }
#pragma unroll
            for (int u = 0; u < TNI/4; u++) {
                float4 v = *(const float4*)&Bs[buf][k][tn + u*4];
                b[u*4+0] = v.x; b[u*4+1] = v.y; b[u*4+2] = v.z; b[u*4+3] = v.w;
            }
#pragma unroll
            for (int i = 0; i < TMI; i++)
#pragma unroll
                for (int j = 0; j < TNI; j++) acc[i][j] = fmaf(a[i], b[j], acc[i][j]);
        }
    };

    LOADA(0); LOADB(0);
    STOREA(0); STOREB(0);
    __syncthreads();
    int buf = 0;
    for (int k0 = BKK; k0 < Kk; k0 += BKK) {
        LOADA(k0); LOADB(k0);
        COMPUTE(buf);
        STOREA(buf ^ 1); STOREB(buf ^ 1);
        __syncthreads();
        buf ^= 1;
    }
    COMPUTE(buf);

#pragma unroll
    for (int i = 0; i < TMI; i++) {
        int row = m0 + tm + i;
#pragma unroll
        for (int j = 0; j < TNI; j++) {
            int col = n0 + tn + j;
            float v = acc[i][j];
            if (EP == 2) { v += bias[col]; v = fmaxf(v, 0.f); }
            C[(size_t)row * ldc + col] = v;
        }
    }
}

// ---------------- prep: z=0 rowsum-sq(user) -> sqU ; z=1 normalize(food) -> XnF ----------------
__global__ void prep_kernel(const float* __restrict__ user, float* __restrict__ sqU,
                            const float* __restrict__ food, float* __restrict__ XnF)
{
    const float* X = blockIdx.z ? food : user;
    int i = blockIdx.x, tid = threadIdx.x;
    float s = 0.f;
    for (int j = tid; j < DIN; j += 256) { float v = X[(size_t)i*DIN + j]; s = fmaf(v, v, s); }
    __shared__ float r[256];
    r[tid] = s; __syncthreads();
    for (int st = 128; st > 0; st >>= 1) { if (tid < st) r[tid] += r[tid + st]; __syncthreads(); }
    if (blockIdx.z == 0) {
        if (tid == 0) sqU[i] = r[0];
    } else {
        float nrm = sqrtf(r[0]);
        for (int j = tid; j < DIN; j += 256) XnF[(size_t)i*DIN + j] = X[(size_t)i*DIN + j] / nrm;
    }
}

// ---------------- tf32 split: z in {user, food, XnF} ----------------
__global__ void split3_kernel(const float* __restrict__ u, float* __restrict__ uh, float* __restrict__ ul,
                              const float* __restrict__ f, float* __restrict__ fh, float* __restrict__ fl,
                              const float* __restrict__ x, float* __restrict__ xh, float* __restrict__ xl)
{
    const float* in = blockIdx.z == 0 ? u : (blockIdx.z == 1 ? f : x);
    float* oh = blockIdx.z == 0 ? uh : (blockIdx.z == 1 ? fh : xh);
    float* ol = blockIdx.z == 0 ? ul : (blockIdx.z == 1 ? fl : xl);
    int i = blockIdx.x * blockDim.x + threadIdx.x;   // float4 index
    float4 v = ((const float4*)in)[i];
    float4 h, l;
    h.x = tf32r(v.x); l.x = tf32r(v.x - h.x);
    h.y = tf32r(v.y); l.y = tf32r(v.y - h.y);
    h.z = tf32r(v.z); l.z = tf32r(v.z - h.z);
    h.w = tf32r(v.w); l.w = tf32r(v.w - h.w);
    ((float4*)oh)[i] = h;
    ((float4*)ol)[i] = l;
}

// ---------------- deterministic total order: (value desc, index asc) ----------------
__device__ __forceinline__ bool better(float a, int ai, float b, int bi)
{
    return (a > b) || (a == b && ai < bi);
}

// ---------------- single-pass top-6, 128 threads (measured-best), z-batched ----------------
__global__ void top6_onepass(const float* __restrict__ S0, const float* __restrict__ S1,
                             int* __restrict__ oI0, float* __restrict__ oV0,
                             int* __restrict__ oI1, float* __restrict__ oV1)
{
    const float* S = blockIdx.z ? S1 : S0;
    int*   oI = blockIdx.z ? oI1 : oI0;
    float* oV = blockIdx.z ? oV1 : oV0;

    __shared__ float sv[128*TOPK];
    __shared__ int   si[128*TOPK];
    __shared__ int   ch[TOPK];
    __shared__ float rv[128];
    __shared__ int   ri[128];

    int row = blockIdx.x, tid = threadIdx.x;
    const float* Sr = S + (size_t)row * NN;

    float lv[TOPK]; int li[TOPK];
#pragma unroll
    for (int t = 0; t < TOPK; t++) { lv[t] = -FLT_MAX; li[t] = 0x7FFFFFFF; }
    for (int j = tid; j < NN; j += 128) {
        float x = Sr[j];
        if (better(x, j, lv[TOPK-1], li[TOPK-1])) {
            lv[TOPK-1] = x; li[TOPK-1] = j;
#pragma unroll
            for (int t = TOPK-1; t > 0; t--) {
                if (better(lv[t], li[t], lv[t-1], li[t-1])) {
                    float tv = lv[t]; lv[t] = lv[t-1]; lv[t-1] = tv;
                    int ti = li[t]; li[t] = li[t-1]; li[t-1] = ti;
                } else break;
            }
        }
    }
#pragma unroll
    for (int t = 0; t < TOPK; t++) { sv[tid*TOPK+t] = lv[t]; si[tid*TOPK+t] = li[t]; }
    __syncthreads();

    for (int t = 0; t < TOPK; t++) {
        float bv = -FLT_MAX; int bi = 0x7FFFFFFF;
#pragma unroll
        for (int u = 0; u < TOPK; u++) {
            int e = tid*TOPK + u;
            int cidx = si[e];
            bool used = false;
            for (int w = 0; w < t; w++) used |= (ch[w] == cidx);
            if (!used && better(sv[e], cidx, bv, bi)) { bv = sv[e]; bi = cidx; }
        }
        rv[tid] = bv; ri[tid] = bi;
        __syncthreads();
        if (tid < 32) {
#pragma unroll
            for (int o = 32; o < 128; o += 32) {
                if (better(rv[tid+o], ri[tid+o], bv, bi)) { bv = rv[tid+o]; bi = ri[tid+o]; }
            }
#pragma unroll
            for (int o = 16; o > 0; o >>= 1) {
                float ov = __shfl_down_sync(0xFFFFFFFFu, bv, o);
                int   oi = __shfl_down_sync(0xFFFFFFFFu, bi, o);
                if (better(ov, oi, bv, bi)) { bv = ov; bi = oi; }
            }
            if (tid == 0) {
                ch[t] = bi;
                oI[row*TOPK + t] = bi;
                oV[row*TOPK + t] = bv;
            }
        }
        __syncthreads();
    }
}

// ---------------- adjacency mask build, z-batched (PROVEN) ----------------
__global__ void clear_masks()
{
    int i = blockIdx.x * blockDim.x + threadIdx.x;
    ((unsigned int*)g_maskU)[i] = 0u;
    ((unsigned int*)g_maskF)[i] = 0u;
}

__global__ void mark_kernel2(const int* __restrict__ idx0, const float* __restrict__ val0,
                             unsigned char* __restrict__ mask0,
                             const int* __restrict__ idx1, const float* __restrict__ val1,
                             unsigned char* __restrict__ mask1)
{
    const int*   idx  = blockIdx.z ? idx1 : idx0;
    const float* val  = blockIdx.z ? val1 : val0;
    unsigned char* mask = blockIdx.z ? mask1 : mask0;
    int needPos = blockIdx.z;
    int i = blockIdx.x * blockDim.x + threadIdx.x;
    if (i >= NN) return;
#pragma unroll
    for (int t = 0; t < TOPK; t++) {
        int j = idx[i*TOPK + t];
        if (j == i) continue;
        if (needPos && !(val[i*TOPK + t] > 0.f)) continue;
        mask[(size_t)i*NN + j] = 1;
        mask[(size_t)j*NN + i] = 1;
    }
}

__global__ void collect_kernel2(const unsigned char* __restrict__ mask0,
                                int* __restrict__ nbr0, int* __restrict__ cnt0,
                                const unsigned char* __restrict__ mask1,
                                int* __restrict__ nbr1, int* __restrict__ cnt1)
{
    const unsigned char* mask = blockIdx.z ? mask1 : mask0;
    int* nbr = blockIdx.z ? nbr1 : nbr0;
    int* cnt = blockIdx.z ? cnt1 : cnt0;
    int warp = (blockIdx.x * blockDim.x + threadIdx.x) >> 5;
    int lane = threadIdx.x & 31;
    if (warp >= NN) return;
    const unsigned char* mr = mask + (size_t)warp * NN;
    int c = 0;
    for (int base = 0; base < NN; base += 32) {
        bool m = mr[base + lane] != 0;
        unsigned b = __ballot_sync(0xFFFFFFFFu, m);
        if (m) nbr[(size_t)warp*MAXD + c + __popc(b & ((1u << lane) - 1u))] = base + lane;
        c += __popc(b);
    }
    if (lane == 0) cnt[warp] = c;
}

// ---------------- sparse attention + aggregate + elu (hub-safe, PROVEN), z-batched ----------------
__global__ void att_agg2(const float* __restrict__ Wh0, const float* __restrict__ s10,
                         const float* __restrict__ s20, const int* __restrict__ nbr0,
                         const int* __restrict__ cnt0, float* __restrict__ out0,
                         const float* __restrict__ Wh1, const float* __restrict__ s11,
                         const float* __restrict__ s21, const int* __restrict__ nbr1,
                         const int* __restrict__ cnt1, float* __restrict__ out1,
                         int rowStride, int nheads)
{
    const float* Wh = blockIdx.z ? Wh1 : Wh0;
    const float* s1 = blockIdx.z ? s11 : s10;
    const float* s2 = blockIdx.z ? s21 : s20;
    const int* nbr  = blockIdx.z ? nbr1 : nbr0;
    const int* cnt  = blockIdx.z ? cnt1 : cnt0;
    float* out      = blockIdx.z ? out1 : out0;

    __shared__ int   sidx[MAXD];
    __shared__ float sw[NH][MAXD];
    __shared__ float hs[NH];
    int i = blockIdx.x, tid = threadIdx.x;
    int wid = tid >> 5, lane = tid & 31;
    int c = cnt[i];

    for (int t = tid; t < c; t += 256) sidx[t] = nbr[(size_t)i*MAXD + t];
    __syncthreads();

    for (int q = tid; q < nheads*c; q += 256) {
        int h = q / c, t = q - h*c;
        float e = s1[h*NN + i] + s2[h*NN + sidx[t]];
        sw[h][t] = (e >= 0.f) ? e : 0.2f * e;
    }
    __syncthreads();

    if (wid < nheads) {
        int h = wid;
        float m = -FLT_MAX;
        for (int t = lane; t < c; t += 32) m = fmaxf(m, sw[h][t]);
#pragma unroll
        for (int o = 16; o > 0; o >>= 1) m = fmaxf(m, __shfl_xor_sync(0xFFFFFFFFu, m, o));
        float s = 0.f;
        for (int t = lane; t < c; t += 32) { float ex = expf(sw[h][t] - m); sw[h][t] = ex; s += ex; }
#pragma unroll
        for (int o = 16; o > 0; o >>= 1) s += __shfl_xor_sync(0xFFFFFFFFu, s, o);
        if (lane == 0) hs[h] = s;
    }
    __syncthreads();

    for (int q = tid; q < nheads*c; q += 256) {
        int h = q / c, t = q - h*c;
        sw[h][t] /= hs[h];
    }
    __syncthreads();

    for (int h = 0; h < nheads; h++) {
        float acc = 0.f;
#pragma unroll 4
        for (int t = 0; t < c; t++)
            acc = fmaf(sw[h][t], Wh[(size_t)sidx[t]*rowStride + h*HID + tid], acc);
        out[(size_t)i*rowStride + h*HID + tid] = (acc > 0.f) ? acc : expm1f(acc);
    }
}

// ---------------- repack W + tf32 split, z-batched ----------------
__global__ void repack_W2(const float* __restrict__ W0, float* __restrict__ Whi0,
                          float* __restrict__ Wlo0,
                          const float* __restrict__ W1, float* __restrict__ Whi1,
                          float* __restrict__ Wlo1)
{
    const float* W = blockIdx.z ? W1 : W0;
    float* Whi = blockIdx.z ? Whi1 : Whi0;
    float* Wlo = blockIdx.z ? Wlo1 : Wlo0;
    int i = blockIdx.x * blockDim.x + threadIdx.x;
    if (i >= DIN*NH*HID) return;
    int d = i / (NH*HID);
    int r = i % (NH*HID);
    int h = r / HID;
    int f = r % HID;
    float v = W[(size_t)h*DIN*HID + (size_t)d*HID + f];
    float hi = tf32r(v);
    Whi[i] = hi;
    Wlo[i] = tf32r(v - hi);
}

__global__ void s1s2_kernel2(const float* __restrict__ WhA, const float* __restrict__ aA,
                             float* __restrict__ s1A, float* __restrict__ s2A,
                             const float* __restrict__ WhB, const float* __restrict__ aB,
                             float* __restrict__ s1B, float* __restrict__ s2B,
                             int rowStride)
{
    const float* Wh = blockIdx.z ? WhB : WhA;
    const float* a  = blockIdx.z ? aB : aA;
    float* s1 = blockIdx.z ? s1B : s1A;
    float* s2 = blockIdx.z ? s2B : s2A;
    int i = blockIdx.x, h = blockIdx.y, f = threadIdx.x;
    float w = Wh[(size_t)i*rowStride + h*HID + f];
    float v1 = w * a[h*2*HID + f];
    float v2 = w * a[h*2*HID + HID + f];
    __shared__ float r1[256], r2[256];
    r1[f] = v1; r2[f] = v2; __syncthreads();
    for (int st = 128; st > 0; st >>= 1) {
        if (f < st) { r1[f] += r1[f+st]; r2[f] += r2[f+st]; }
        __syncthreads();
    }
    if (f == 0) { s1[h*NN + i] = r1[0]; s2[h*NN + i] = r2[0]; }
}

// ---------------- MLP pieces (PROVEN) ----------------
__global__ void concat_kernel()
{
    int i = blockIdx.x, c = threadIdx.x;
    g_pair[(size_t)i*512 + c] = (c < HID) ? g_embU[(size_t)i*HID + c]
                                          : g_embF[(size_t)i*HID + (c - HID)];
}

__global__ void mlp_final_kernel(const float* __restrict__ act, const float* __restrict__ W,
                                 const float* __restrict__ b, float* __restrict__ out)
{
    int i = blockIdx.x, tid = threadIdx.x;
    float v = act[(size_t)i*128 + tid] * W[tid];
    __shared__ float r[128];
    r[tid] = v; __syncthreads();
    for (int st = 64; st > 0; st >>= 1) { if (tid < st) r[tid] += r[tid+st]; __syncthreads(); }
    if (tid == 0) out[i] = r[0] + b[0];
}

// ---------------- host launch ----------------
template <typename T>
static T* sym(const void* s)
{
    void* p = nullptr;
    cudaGetSymbolAddress(&p, s);
    return (T*)p;
}

extern "C" void kernel_launch(void* const* d_in, const int* in_sizes, int n_in,
                              void* d_out, int out_size)
{
    const float* user_nodes = (const float*)d_in[0];
    const float* food_nodes = (const float*)d_in[1];
    const float* user_W_h   = (const float*)d_in[2];
    const float* user_a_h   = (const float*)d_in[3];
    const float* user_W_o   = (const float*)d_in[4];
    const float* user_a_o   = (const float*)d_in[5];
    const float* food_W_h   = (const float*)d_in[6];
    const float* food_a_h   = (const float*)d_in[7];
    const float* food_W_o   = (const float*)d_in[8];
    const float* food_a_o   = (const float*)d_in[9];
    const float* mlp_W0 = (const float*)d_in[10];
    const float* mlp_b0 = (const float*)d_in[11];
    const float* mlp_W1 = (const float*)d_in[12];
    const float* mlp_b1 = (const float*)d_in[13];
    const float* mlp_W2 = (const float*)d_in[14];
    const float* mlp_b2 = (const float*)d_in[15];
    const float* mlp_W3 = (const float*)d_in[16];
    const float* mlp_b3 = (const float*)d_in[17];
    float* out = (float*)d_out;

    float* pZero  = sym<float>(g_zero);
    float* pSqU   = sym<float>(g_sqU);
    float* pXnF   = sym<float>(g_XnF);
    float* pSimU  = sym<float>(g_simU);
    float* pSimF  = sym<float>(g_simF);
    int*   pTidxU = sym<int>(g_tidxU);
    float* pTvalU = sym<float>(g_tvalU);
    int*   pTidxF = sym<int>(g_tidxF);
    float* pTvalF = sym<float>(g_tvalF);
    unsigned char* pMaskU = sym<unsigned char>(g_maskU);
    unsigned char* pMaskF = sym<unsigned char>(g_maskF);
    int*   pNbrU = sym<int>(g_nbrU);
    int*   pCntU = sym<int>(g_cntU);
    int*   pNbrF = sym<int>(g_nbrF);
    int*   pCntF = sym<int>(g_cntF);
    float* pUhi = sym<float>(g_uhi);  float* pUlo = sym<float>(g_ulo);
    float* pFhi = sym<float>(g_fhi);  float* pFlo = sym<float>(g_flo);
    float* pXhi = sym<float>(g_xhi);  float* pXlo = sym<float>(g_xlo);
    float* pWhiU = sym<float>(g_WhiU); float* pWloU = sym<float>(g_WloU);
    float* pWhiF = sym<float>(g_WhiF); float* pWloF = sym<float>(g_WloF);
    float* pWhU  = sym<float>(g_WhU);
    float* pWhF  = sym<float>(g_WhF);
    float* pS1U  = sym<float>(g_s1U);
    float* pS2U  = sym<float>(g_s2U);
    float* pS1F  = sym<float>(g_s1F);
    float* pS2F  = sym<float>(g_s2F);
    float* pHidU = sym<float>(g_hidU);
    float* pHidF = sym<float>(g_hidF);
    float* pWhoU = sym<float>(g_WhoU);
    float* pWhoF = sym<float>(g_WhoF);
    float* pS1oU = sym<float>(g_s1oU);
    float* pS2oU = sym<float>(g_s2oU);
    float* pS1oF = sym<float>(g_s1oF);
    float* pS2oF = sym<float>(g_s2oF);
    float* pEmbU = sym<float>(g_embU);
    float* pEmbF = sym<float>(g_embF);
    float* pPair = sym<float>(g_pair);
    float* pAct0 = sym<float>(g_act0);
    float* pAct1 = sym<float>(g_act1);
    float* pAct2 = sym<float>(g_act2);

    const int NTRI = (NN/128) * (NN/128 + 1) / 2;   // 136 upper-tri tiles

    // ---- graph build ----
    prep_kernel<<<dim3(NN,1,2), 256>>>(user_nodes, pSqU, food_nodes, pXnF);
    split3_kernel<<<dim3(NN*DIN/4/256,1,3), 256>>>(user_nodes, pUhi, pUlo,
                                                   food_nodes, pFhi, pFlo,
                                                   pXnF, pXhi, pXlo);
    // batched sims on tensor cores: z=0 user euclid (-d^2), z=1 food cosine x2 (sq=0)
    mma_gemm2<true, 1, true><<<dim3(NTRI,1,2), 256>>>(
        pUhi, pUlo, pUhi, pUlo, pSimU, pSqU,
        pXhi, pXlo, pXhi, pXlo, pSimF, pZero,
        NN, NN, DIN, DIN, DIN, NN);
    top6_onepass<<<dim3(NN,1,2), 128>>>(pSimU, pSimF, pTidxU, pTvalU, pTidxF, pTvalF);

    clear_masks<<<(NN*NN/4)/256, 256>>>();
    mark_kernel2<<<dim3((NN+255)/256,1,2), 256>>>(pTidxU, pTvalU, pMaskU,
                                                  pTidxF, pTvalF, pMaskF);
    collect_kernel2<<<dim3(NN*32/256,1,2), 256>>>(pMaskU, pNbrU, pCntU,
                                                  pMaskF, pNbrF, pCntF);

    // ---- GAT hidden layer (user & food batched) ----
    repack_W2<<<dim3((DIN*NH*HID+255)/256,1,2), 256>>>(user_W_h, pWhiU, pWloU,
                                                       food_W_h, pWhiF, pWloF);
    mma_gemm2<false, 0, false><<<dim3((NH*HID)/128, NN/128, 2), 256>>>(
        pUhi, pUlo, pWhiU, pWloU, pWhU, nullptr,
        pFhi, pFlo, pWhiF, pWloF, pWhF, nullptr,
        NN, NH*HID, DIN, DIN, NH*HID, NH*HID);
    s1s2_kernel2<<<dim3(NN, NH, 2), 256>>>(pWhU, user_a_h, pS1U, pS2U,
                                           pWhF, food_a_h, pS1F, pS2F, NH*HID);
    att_agg2<<<dim3(NN,1,2), 256>>>(pWhU, pS1U, pS2U, pNbrU, pCntU, pHidU,
                                    pWhF, pS1F, pS2F, pNbrF, pCntF, pHidF,
                                    NH*HID, NH);

    // ---- GAT output layer (user & food batched; SIMT) ----
    sgemm2<false, 0, 64,64,4,4><<<dim3(HID/64, NN/64, 2), 256>>>(
        pHidU, user_W_o, pWhoU, nullptr,
        pHidF, food_W_o, pWhoF, nullptr,
        NN, HID, NH*HID, NH*HID, HID, HID);
    s1s2_kernel2<<<dim3(NN, 1, 2), 256>>>(pWhoU, user_a_o, pS1oU, pS2oU,
                                          pWhoF, food_a_o, pS1oF, pS2oF, HID);
    att_agg2<<<dim3(NN,1,2), 256>>>(pWhoU, pS1oU, pS2oU, pNbrU, pCntU, pEmbU,
                                    pWhoF, pS1oF, pS2oF, pNbrF, pCntF, pEmbF,
                                    HID, 1);

    // ---- MLP (SIMT) ----
    concat_kernel<<<NN, 512>>>();
    sgemm2<false, 2, 64,64,4,4><<<dim3(512/64, NN/64, 1), 256>>>(
        pPair, mlp_W0, pAct0, mlp_b0,
        pPair, mlp_W0, pAct0, mlp_b0,
        NN, 512, 512, 512, 512, 512);
    sgemm2<false, 2, 64,64,4,4><<<dim3(256/64, NN/64, 1), 256>>>(
        pAct0, mlp_W1, pAct1, mlp_b1,
        pAct0, mlp_W1, pAct1, mlp_b1,
        NN, 256, 512, 512, 256, 256);
    sgemm2<false, 2, 64,64,4,4><<<dim3(128/64, NN/64, 1), 256>>>(
        pAct1, mlp_W2, pAct2, mlp_b2,
        pAct1, mlp_W2, pAct2, mlp_b2,
        NN, 128, 256, 256, 128, 128);
    mlp_final_kernel<<<NN, 128>>>(pAct2, mlp_W3, mlp_b3, out);
}

// round 17
// speedup vs baseline: 1.0911x; 1.0184x over previous
#include <cuda_runtime.h>
#include <math.h>
#include <float.h>

// ---------------- problem constants ----------------
#define NN   2048
#define DIN  512
#define HID  256
#define NH   4
#define TOPK 6      // k+1
#define MAXD 2048   // no truncation (kNN hubness gives in-degrees in the hundreds)
#define BKK  16     // SIMT sgemm slab
#define KSLAB 8     // mma slab

// ---------------- device scratch (static, no allocs; zero-initialized) ----------------
__device__ float g_zero[NN];       // stays all-zero
__device__ float g_sqU[NN];
__device__ float g_XnF[NN*DIN];
__device__ float g_simU[NN*NN];
__device__ float g_simF[NN*NN];
__device__ int   g_tidxU[NN*TOPK];
__device__ float g_tvalU[NN*TOPK];
__device__ int   g_tidxF[NN*TOPK];
__device__ float g_tvalF[NN*TOPK];
__device__ unsigned char g_maskU[NN*NN];
__device__ unsigned char g_maskF[NN*NN];
__device__ int   g_nbrU[NN*MAXD];
__device__ int   g_cntU[NN];
__device__ int   g_nbrF[NN*MAXD];
__device__ int   g_cntF[NN];
// tf32 split buffers
__device__ float g_uhi[NN*DIN];
__device__ float g_ulo[NN*DIN];
__device__ float g_fhi[NN*DIN];
__device__ float g_flo[NN*DIN];
__device__ float g_xhi[NN*DIN];
__device__ float g_xlo[NN*DIN];
__device__ float g_WhiU[DIN*NH*HID];
__device__ float g_WloU[DIN*NH*HID];
__device__ float g_WhiF[DIN*NH*HID];
__device__ float g_WloF[DIN*NH*HID];
__device__ float g_WhU[NN*NH*HID];
__device__ float g_WhF[NN*NH*HID];
__device__ float g_s1U[NH*NN];
__device__ float g_s2U[NH*NN];
__device__ float g_s1F[NH*NN];
__device__ float g_s2F[NH*NN];
__device__ float g_hidU[NN*NH*HID];
__device__ float g_hidF[NN*NH*HID];
__device__ float g_WhoU[NN*HID];
__device__ float g_WhoF[NN*HID];
__device__ float g_s1oU[NN];
__device__ float g_s2oU[NN];
__device__ float g_s1oF[NN];
__device__ float g_s2oF[NN];
__device__ float g_embU[NN*HID];
__device__ float g_embF[NN*HID];
__device__ float g_pair[NN*512];
__device__ float g_act0[NN*512];
__device__ float g_act1[NN*256];
__device__ float g_act2[NN*128];

__device__ __forceinline__ float tf32r(float x)
{
    float y;
    asm("cvt.rna.tf32.f32 %0, %1;" : "=f"(y) : "f"(x));
    return y;
}

#define MMA_TF32(c, a0, a1, a2, a3, b0, b1) \
    asm volatile("mma.sync.aligned.m16n8k8.row.col.f32.tf32.tf32.f32 " \
                 "{%0,%1,%2,%3}, {%4,%5,%6,%7}, {%8,%9}, {%0,%1,%2,%3};" \
                 : "+f"(c[0]), "+f"(c[1]), "+f"(c[2]), "+f"(c[3]) \
                 : "r"(a0), "r"(a1), "r"(a2), "r"(a3), "r"(b0), "r"(b1))

// smem layout (floats) per stage (fragment-major, validated R14):
#define OFF_AL 1024
#define OFF_BH 2048
#define OFF_BL 3104
#define STAGE  4160

// ---------------- merged tensor-core GEMM (3xTF32), one launch for sims + Wh ----------------
// blockIdx.z: 0 = user sim (TB,EP1,SYM), 1 = food sim (TB,EP1,SYM, sq=0 -> 2*cos),
//             2 = user Wh (plain), 3 = food Wh (plain).
// Per-output arithmetic order identical to the validated R14 kernel.
__launch_bounds__(256)
__global__ void megamma(const float* __restrict__ uhi, const float* __restrict__ ulo,
                        const float* __restrict__ xhi, const float* __restrict__ xlo,
                        const float* __restrict__ fhi, const float* __restrict__ flo,
                        const float* __restrict__ WhiU, const float* __restrict__ WloU,
                        const float* __restrict__ WhiF, const float* __restrict__ WloF,
                        float* __restrict__ simU, float* __restrict__ simF,
                        float* __restrict__ WhUo, float* __restrict__ WhFo,
                        const float* __restrict__ sqU, const float* __restrict__ zero)
{
    const int z = blockIdx.z;
    const bool SIMS = (z < 2);

    const float *Ah, *Al, *Bh, *Bl, *sq = nullptr;
    float* C;
    int ldb, ldc;
    if (z == 0)      { Ah = uhi; Al = ulo; Bh = uhi; Bl = ulo; C = simU; sq = sqU;  ldb = DIN;    ldc = NN; }
    else if (z == 1) { Ah = xhi; Al = xlo; Bh = xhi; Bl = xlo; C = simF; sq = zero; ldb = DIN;    ldc = NN; }
    else if (z == 2) { Ah = uhi; Al = ulo; Bh = WhiU; Bl = WloU; C = WhUo;          ldb = NH*HID; ldc = NH*HID; }
    else             { Ah = fhi; Al = flo; Bh = WhiF; Bl = WloF; C = WhFo;          ldb = NH*HID; ldc = NH*HID; }
    const int lda = DIN;

    int bx, by;
    if (SIMS) {
        int nb = NN / 128;                 // 16
        int idx = blockIdx.x, bi = 0;
        while (idx >= nb - bi) { idx -= nb - bi; bi++; }
        by = bi; bx = bi + idx;            // 136 tri blocks
    } else {
        if (blockIdx.x >= 128) return;     // Wh: 8 x 16 = 128 blocks
        bx = blockIdx.x & 7;
        by = blockIdx.x >> 3;
    }
    const int m0 = by * 128, n0 = bx * 128;

    __shared__ float smemS[2*STAGE];       // 33280 B

    const int tid = threadIdx.x;
    const int wid = tid >> 5, lane = tid & 31;
    const int g = lane >> 2, t4 = lane & 3;
    const int wmb = (wid >> 2) * 4;
    const int wnb = (wid & 3) * 4;
    const int wm = (wid >> 2) * 64;
    const int wn = (wid & 3) * 32;

    // A frag-store indices
    const int ar  = tid >> 1;
    const int ac4 = (tid & 1) * 4;
    const int abase = (ar >> 4)*128 + (ar & 7)*16 + (ac4 >> 2)*2 + ((ar >> 3) & 1);
    // B indices (TB variant for sims, K-major variant for Wh)
    const int br  = tid >> 1;
    const int bc4 = (tid & 1) * 4;
    const int bbaseT = (br >> 3)*66 + (br & 7)*8 + (bc4 >> 2);
    const int bk  = tid >> 5;
    const int bcn = (tid & 31) * 4;
    const int bbaseF = (bcn >> 3)*66 + (bcn & 7)*8 + (bk & 3)*2 + (bk >> 2);

    float4 vah, vala, vbh, vbl;
    auto LOADAB = [&](int k0) {
        vah  = *(const float4*)(Ah + (size_t)(m0 + ar)*lda + k0 + ac4);
        vala = *(const float4*)(Al + (size_t)(m0 + ar)*lda + k0 + ac4);
        if (SIMS) {
            vbh = *(const float4*)(Bh + (size_t)(n0 + br)*ldb + k0 + bc4);
            vbl = *(const float4*)(Bl + (size_t)(n0 + br)*ldb + k0 + bc4);
        } else {
            vbh = *(const float4*)(Bh + (size_t)(k0 + bk)*ldb + n0 + bcn);
            vbl = *(const float4*)(Bl + (size_t)(k0 + bk)*ldb + n0 + bcn);
        }
    };
    auto STOREAB = [&](int s) {
        float* AH = smemS + s*STAGE;
        float* AL = AH + OFF_AL;
        float* BH = AH + OFF_BH;
        float* BL = AH + OFF_BL;
        AH[abase+0]  = vah.x;  AH[abase+4]  = vah.y;  AH[abase+8]  = vah.z;  AH[abase+12] = vah.w;
        AL[abase+0]  = vala.x; AL[abase+4]  = vala.y; AL[abase+8]  = vala.z; AL[abase+12] = vala.w;
        if (SIMS) {
            BH[bbaseT+0] = vbh.x; BH[bbaseT+2] = vbh.y; BH[bbaseT+4] = vbh.z; BH[bbaseT+6] = vbh.w;
            BL[bbaseT+0] = vbl.x; BL[bbaseT+2] = vbl.y; BL[bbaseT+4] = vbl.z; BL[bbaseT+6] = vbl.w;
        } else {
            BH[bbaseF+0]  = vbh.x; BH[bbaseF+8]  = vbh.y;
            BH[bbaseF+16] = vbh.z; BH[bbaseF+24] = vbh.w;
            BL[bbaseF+0]  = vbl.x; BL[bbaseF+8]  = vbl.y;
            BL[bbaseF+16] = vbl.z; BL[bbaseF+24] = vbl.w;
        }
    };

    float acc[4][4][4];
#pragma unroll
    for (int i = 0; i < 4; i++)
#pragma unroll
        for (int j = 0; j < 4; j++)
#pragma unroll
            for (int e = 0; e < 4; e++) acc[i][j][e] = 0.f;

    auto COMPUTE = [&](int s) {
        const float* base = smemS + s*STAGE;
        const float4* AH4 = (const float4*)base;
        const float4* AL4 = (const float4*)(base + OFF_AL);
        const float*  BHf = base + OFF_BH;
        const float*  BLf = base + OFF_BL;
        unsigned bh[4][2], bl[4][2];
#pragma unroll
        for (int nt = 0; nt < 4; nt++) {
            float2 h = *(const float2*)&BHf[(wnb + nt)*66 + lane*2];
            float2 l = *(const float2*)&BLf[(wnb + nt)*66 + lane*2];
            bh[nt][0] = __float_as_uint(h.x); bh[nt][1] = __float_as_uint(h.y);
            bl[nt][0] = __float_as_uint(l.x); bl[nt][1] = __float_as_uint(l.y);
        }
#pragma unroll
        for (int mt = 0; mt < 4; mt++) {
            float4 ha = AH4[(wmb + mt)*32 + lane];
            float4 la = AL4[(wmb + mt)*32 + lane];
            unsigned ah0 = __float_as_uint(ha.x), ah1 = __float_as_uint(ha.y);
            unsigned ah2 = __float_as_uint(ha.z), ah3 = __float_as_uint(ha.w);
            unsigned al0 = __float_as_uint(la.x), al1 = __float_as_uint(la.y);
            unsigned al2 = __float_as_uint(la.z), al3 = __float_as_uint(la.w);
#pragma unroll
            for (int nt = 0; nt < 4; nt++) {
                MMA_TF32(acc[mt][nt], al0, al1, al2, al3, bh[nt][0], bh[nt][1]);
                MMA_TF32(acc[mt][nt], ah0, ah1, ah2, ah3, bl[nt][0], bl[nt][1]);
                MMA_TF32(acc[mt][nt], ah0, ah1, ah2, ah3, bh[nt][0], bh[nt][1]);
            }
        }
    };

    LOADAB(0);
    STOREAB(0);
    __syncthreads();
    int s = 0;
    for (int k0 = KSLAB; k0 < DIN; k0 += KSLAB) {
        LOADAB(k0);
        COMPUTE(s);
        STOREAB(s ^ 1);
        __syncthreads();
        s ^= 1;
    }
    COMPUTE(s);

    // ---- normal (row-major) writes ----
#pragma unroll
    for (int mt = 0; mt < 4; mt++) {
#pragma unroll
        for (int nt = 0; nt < 4; nt++) {
            int r0 = m0 + wm + 16*mt + g;
            int c0 = n0 + wn + 8*nt + 2*t4;
#pragma unroll
            for (int e = 0; e < 4; e++) {
                int row = r0 + (e >> 1) * 8;
                int col = c0 + (e & 1);
                float v = acc[mt][nt][e];
                if (SIMS) v = -((sq[row] + sq[col]) - 2.f * v);
                C[(size_t)row * ldc + col] = v;
            }
        }
    }

    // ---- mirror writes (sims, off-diagonal), coalesced via smem staging ----
    if (SIMS && bx != by) {
        float* Sst = smemS;
#pragma unroll
        for (int p = 0; p < 4; p++) {
            __syncthreads();
            if ((wn >> 5) == p) {
#pragma unroll
                for (int mt = 0; mt < 4; mt++) {
#pragma unroll
                    for (int nt = 0; nt < 4; nt++) {
                        int rl0 = wm + 16*mt + g;
                        int cl0 = ((wn + 8*nt + 2*t4) & 31);
#pragma unroll
                        for (int e = 0; e < 4; e++) {
                            int rl = rl0 + (e >> 1) * 8;
                            int cl = cl0 + (e & 1);
                            float v = acc[mt][nt][e];
                            v = -((sq[m0 + rl] + sq[n0 + p*32 + cl]) - 2.f * v);
                            Sst[cl*132 + rl] = v;
                        }
                    }
                }
            }
            __syncthreads();
            for (int q = tid; q < 32*128; q += 256) {
                int rm = q >> 7, cm = q & 127;
                C[(size_t)(n0 + p*32 + rm) * ldc + (m0 + cm)] = Sst[rm*132 + cm];
            }
        }
    }
}

// ---------------- SIMT SGEMM (64x64 tile; proven) for W_o + MLP ----------------
template<bool TB, int EP, int TBM, int TBN, int TMI, int TNI>
__launch_bounds__(256, 2)
__global__ void sgemm2(const float* __restrict__ A0, const float* __restrict__ B0,
                       float* __restrict__ C0, const float* __restrict__ bias0,
                       const float* __restrict__ A1, const float* __restrict__ B1,
                       float* __restrict__ C1, const float* __restrict__ bias1,
                       int M, int Nn, int Kk, int lda, int ldb, int ldc)
{
    static_assert((TBM/TMI)*(TBN/TNI) == 256, "thread count");
    const float* A    = blockIdx.z ? A1 : A0;
    const float* B    = blockIdx.z ? B1 : B0;
    float*       C    = blockIdx.z ? C1 : C0;
    const float* bias = blockIdx.z ? bias1 : bias0;

    __shared__ float As[2][BKK][TBM+4];
    __shared__ float Bs[2][BKK][TBN+4];
    const int tid = threadIdx.x;
    const int m0 = blockIdx.y * TBM, n0 = blockIdx.x * TBN;
    const int tm = (tid / (TBN/TNI)) * TMI;
    const int tn = (tid % (TBN/TNI)) * TNI;

    const int AIT = TBM*BKK/4/256 > 0 ? TBM*BKK/4/256 : 1;
    const int BIT = TBN*BKK/4/256 > 0 ? TBN*BKK/4/256 : 1;
    float4 ra[AIT], rb[BIT];

    auto LOADA = [&](int k0) {
#pragma unroll
        for (int it = 0; it < AIT; it++) {
            int q = tid + it*256;
            int r = q >> 2, c4 = (q & 3) * 4;
            ra[it] = *(const float4*)(A + (size_t)(m0 + r)*lda + k0 + c4);
        }
    };
    auto STOREA = [&](int buf) {
#pragma unroll
        for (int it = 0; it < AIT; it++) {
            int q = tid + it*256;
            int r = q >> 2, c4 = (q & 3) * 4;
            As[buf][c4+0][r] = ra[it].x; As[buf][c4+1][r] = ra[it].y;
            As[buf][c4+2][r] = ra[it].z; As[buf][c4+3][r] = ra[it].w;
        }
    };
    auto LOADB = [&](int k0) {
#pragma unroll
        for (int it = 0; it < BIT; it++) {
            int q = tid + it*256;
            if (!TB) {
                int r = q / (TBN/4), cn = (q % (TBN/4)) * 4;
                rb[it] = *(const float4*)(B + (size_t)(k0 + r)*ldb + n0 + cn);
            } else {
                int r = q >> 2, c4 = (q & 3) * 4;
                rb[it] = *(const float4*)(B + (size_t)(n0 + r)*ldb + k0 + c4);
            }
        }
    };
    auto STOREB = [&](int buf) {
#pragma unroll
        for (int it = 0; it < BIT; it++) {
            int q = tid + it*256;
            if (!TB) {
                int r = q / (TBN/4), cn = (q % (TBN/4)) * 4;
                Bs[buf][r][cn+0] = rb[it].x; Bs[buf][r][cn+1] = rb[it].y;
                Bs[buf][r][cn+2] = rb[it].z; Bs[buf][r][cn+3] = rb[it].w;
            } else {
                int r = q >> 2, c4 = (q & 3) * 4;
                Bs[buf][c4+0][r] = rb[it].x; Bs[buf][c4+1][r] = rb[it].y;
                Bs[buf][c4+2][r] = rb[it].z; Bs[buf][c4+3][r] = rb[it].w;
            }
        }
    };

    float acc[TMI][TNI];
#pragma unroll
    for (int i = 0; i < TMI; i++)
#pragma unroll
        for (int j = 0; j < TNI; j++) acc[i][j] = 0.f;

    auto COMPUTE = [&](int buf) {
#pragma unroll
        for (int k = 0; k < BKK; k++) {
            float a[TMI], b[TNI];
#pragma unroll
            for (int u = 0; u < TMI/4; u++) {
                float4 v = *(const float4*)&As[buf][k][tm + u*4];
                a[u*4+0] = v.x; a[u*4+1] = v.y; a[u*4+2] = v.z; a[u*4+3] = v.w;
            }
#pragma unroll
            for (int u = 0; u < TNI/4; u++) {
                float4 v = *(const float4*)&Bs[buf][k][tn + u*4];
                b[u*4+0] = v.x; b[u*4+1] = v.y; b[u*4+2] = v.z; b[u*4+3] = v.w;
            }
#pragma unroll
            for (int i = 0; i < TMI; i++)
#pragma unroll
                for (int j = 0; j < TNI; j++) acc[i][j] = fmaf(a[i], b[j], acc[i][j]);
        }
    };

    LOADA(0); LOADB(0);
    STOREA(0); STOREB(0);
    __syncthreads();
    int buf = 0;
    for (int k0 = BKK; k0 < Kk; k0 += BKK) {
        LOADA(k0); LOADB(k0);
        COMPUTE(buf);
        STOREA(buf ^ 1); STOREB(buf ^ 1);
        __syncthreads();
        buf ^= 1;
    }
    COMPUTE(buf);

#pragma unroll
    for (int i = 0; i < TMI; i++) {
        int row = m0 + tm + i;
#pragma unroll
        for (int j = 0; j < TNI; j++) {
            int col = n0 + tn + j;
            float v = acc[i][j];
            if (EP == 2) { v += bias[col]; v = fmaxf(v, 0.f); }
            C[(size_t)row * ldc + col] = v;
        }
    }
}

// ---------------- prep: z=0 rowsum-sq(user) -> sqU ; z=1 normalize(food) -> XnF ----------------
__global__ void prep_kernel(const float* __restrict__ user, float* __restrict__ sqU,
                            const float* __restrict__ food, float* __restrict__ XnF)
{
    const float* X = blockIdx.z ? food : user;
    int i = blockIdx.x, tid = threadIdx.x;
    float s = 0.f;
    for (int j = tid; j < DIN; j += 256) { float v = X[(size_t)i*DIN + j]; s = fmaf(v, v, s); }
    __shared__ float r[256];
    r[tid] = s; __syncthreads();
    for (int st = 128; st > 0; st >>= 1) { if (tid < st) r[tid] += r[tid + st]; __syncthreads(); }
    if (blockIdx.z == 0) {
        if (tid == 0) sqU[i] = r[0];
    } else {
        float nrm = sqrtf(r[0]);
        for (int j = tid; j < DIN; j += 256) XnF[(size_t)i*DIN + j] = X[(size_t)i*DIN + j] / nrm;
    }
}

// ---------------- tf32 split: z in {user, food, XnF} ----------------
__global__ void split3_kernel(const float* __restrict__ u, float* __restrict__ uh, float* __restrict__ ul,
                              const float* __restrict__ f, float* __restrict__ fh, float* __restrict__ fl,
                              const float* __restrict__ x, float* __restrict__ xh, float* __restrict__ xl)
{
    const float* in = blockIdx.z == 0 ? u : (blockIdx.z == 1 ? f : x);
    float* oh = blockIdx.z == 0 ? uh : (blockIdx.z == 1 ? fh : xh);
    float* ol = blockIdx.z == 0 ? ul : (blockIdx.z == 1 ? fl : xl);
    int i = blockIdx.x * blockDim.x + threadIdx.x;   // float4 index
    float4 v = ((const float4*)in)[i];
    float4 h, l;
    h.x = tf32r(v.x); l.x = tf32r(v.x - h.x);
    h.y = tf32r(v.y); l.y = tf32r(v.y - h.y);
    h.z = tf32r(v.z); l.z = tf32r(v.z - h.z);
    h.w = tf32r(v.w); l.w = tf32r(v.w - h.w);
    ((float4*)oh)[i] = h;
    ((float4*)ol)[i] = l;
}

// ---------------- deterministic total order: (value desc, index asc) ----------------
__device__ __forceinline__ bool better(float a, int ai, float b, int bi)
{
    return (a > b) || (a == b && ai < bi);
}

// ---------------- single-pass top-6, 128 threads (measured-best), z-batched ----------------
__global__ void top6_onepass(const float* __restrict__ S0, const float* __restrict__ S1,
                             int* __restrict__ oI0, float* __restrict__ oV0,
                             int* __restrict__ oI1, float* __restrict__ oV1)
{
    const float* S = blockIdx.z ? S1 : S0;
    int*   oI = blockIdx.z ? oI1 : oI0;
    float* oV = blockIdx.z ? oV1 : oV0;

    __shared__ float sv[128*TOPK];
    __shared__ int   si[128*TOPK];
    __shared__ int   ch[TOPK];
    __shared__ float rv[128];
    __shared__ int   ri[128];

    int row = blockIdx.x, tid = threadIdx.x;
    const float* Sr = S + (size_t)row * NN;

    float lv[TOPK]; int li[TOPK];
#pragma unroll
    for (int t = 0; t < TOPK; t++) { lv[t] = -FLT_MAX; li[t] = 0x7FFFFFFF; }
    for (int j = tid; j < NN; j += 128) {
        float x = Sr[j];
        if (better(x, j, lv[TOPK-1], li[TOPK-1])) {
            lv[TOPK-1] = x; li[TOPK-1] = j;
#pragma unroll
            for (int t = TOPK-1; t > 0; t--) {
                if (better(lv[t], li[t], lv[t-1], li[t-1])) {
                    float tv = lv[t]; lv[t] = lv[t-1]; lv[t-1] = tv;
                    int ti = li[t]; li[t] = li[t-1]; li[t-1] = ti;
                } else break;
            }
        }
    }
#pragma unroll
    for (int t = 0; t < TOPK; t++) { sv[tid*TOPK+t] = lv[t]; si[tid*TOPK+t] = li[t]; }
    __syncthreads();

    for (int t = 0; t < TOPK; t++) {
        float bv = -FLT_MAX; int bi = 0x7FFFFFFF;
#pragma unroll
        for (int u = 0; u < TOPK; u++) {
            int e = tid*TOPK + u;
            int cidx = si[e];
            bool used = false;
            for (int w = 0; w < t; w++) used |= (ch[w] == cidx);
            if (!used && better(sv[e], cidx, bv, bi)) { bv = sv[e]; bi = cidx; }
        }
        rv[tid] = bv; ri[tid] = bi;
        __syncthreads();
        if (tid < 32) {
#pragma unroll
            for (int o = 32; o < 128; o += 32) {
                if (better(rv[tid+o], ri[tid+o], bv, bi)) { bv = rv[tid+o]; bi = ri[tid+o]; }
            }
#pragma unroll
            for (int o = 16; o > 0; o >>= 1) {
                float ov = __shfl_down_sync(0xFFFFFFFFu, bv, o);
                int   oi = __shfl_down_sync(0xFFFFFFFFu, bi, o);
                if (better(ov, oi, bv, bi)) { bv = ov; bi = oi; }
            }
            if (tid == 0) {
                ch[t] = bi;
                oI[row*TOPK + t] = bi;
                oV[row*TOPK + t] = bv;
            }
        }
        __syncthreads();
    }
}

// ---------------- adjacency mask build, z-batched (PROVEN) ----------------
__global__ void clear_masks()
{
    int i = blockIdx.x * blockDim.x + threadIdx.x;
    ((unsigned int*)g_maskU)[i] = 0u;
    ((unsigned int*)g_maskF)[i] = 0u;
}

__global__ void mark_kernel2(const int* __restrict__ idx0, const float* __restrict__ val0,
                             unsigned char* __restrict__ mask0,
                             const int* __restrict__ idx1, const float* __restrict__ val1,
                             unsigned char* __restrict__ mask1)
{
    const int*   idx  = blockIdx.z ? idx1 : idx0;
    const float* val  = blockIdx.z ? val1 : val0;
    unsigned char* mask = blockIdx.z ? mask1 : mask0;
    int needPos = blockIdx.z;
    int i = blockIdx.x * blockDim.x + threadIdx.x;
    if (i >= NN) return;
#pragma unroll
    for (int t = 0; t < TOPK; t++) {
        int j = idx[i*TOPK + t];
        if (j == i) continue;
        if (needPos && !(val[i*TOPK + t] > 0.f)) continue;
        mask[(size_t)i*NN + j] = 1;
        mask[(size_t)j*NN + i] = 1;
    }
}

__global__ void collect_kernel2(const unsigned char* __restrict__ mask0,
                                int* __restrict__ nbr0, int* __restrict__ cnt0,
                                const unsigned char* __restrict__ mask1,
                                int* __restrict__ nbr1, int* __restrict__ cnt1)
{
    const unsigned char* mask = blockIdx.z ? mask1 : mask0;
    int* nbr = blockIdx.z ? nbr1 : nbr0;
    int* cnt = blockIdx.z ? cnt1 : cnt0;
    int warp = (blockIdx.x * blockDim.x + threadIdx.x) >> 5;
    int lane = threadIdx.x & 31;
    if (warp >= NN) return;
    const unsigned char* mr = mask + (size_t)warp * NN;
    int c = 0;
    for (int base = 0; base < NN; base += 32) {
        bool m = mr[base + lane] != 0;
        unsigned b = __ballot_sync(0xFFFFFFFFu, m);
        if (m) nbr[(size_t)warp*MAXD + c + __popc(b & ((1u << lane) - 1u))] = base + lane;
        c += __popc(b);
    }
    if (lane == 0) cnt[warp] = c;
}

// ---------------- sparse attention + aggregate + elu (hub-safe, PROVEN), z-batched ----------------
__global__ void att_agg2(const float* __restrict__ Wh0, const float* __restrict__ s10,
                         const float* __restrict__ s20, const int* __restrict__ nbr0,
                         const int* __restrict__ cnt0, float* __restrict__ out0,
                         const float* __restrict__ Wh1, const float* __restrict__ s11,
                         const float* __restrict__ s21, const int* __restrict__ nbr1,
                         const int* __restrict__ cnt1, float* __restrict__ out1,
                         int rowStride, int nheads)
{
    const float* Wh = blockIdx.z ? Wh1 : Wh0;
    const float* s1 = blockIdx.z ? s11 : s10;
    const float* s2 = blockIdx.z ? s21 : s20;
    const int* nbr  = blockIdx.z ? nbr1 : nbr0;
    const int* cnt  = blockIdx.z ? cnt1 : cnt0;
    float* out      = blockIdx.z ? out1 : out0;

    __shared__ int   sidx[MAXD];
    __shared__ float sw[NH][MAXD];
    __shared__ float hs[NH];
    int i = blockIdx.x, tid = threadIdx.x;
    int wid = tid >> 5, lane = tid & 31;
    int c = cnt[i];

    for (int t = tid; t < c; t += 256) sidx[t] = nbr[(size_t)i*MAXD + t];
    __syncthreads();

    for (int q = tid; q < nheads*c; q += 256) {
        int h = q / c, t = q - h*c;
        float e = s1[h*NN + i] + s2[h*NN + sidx[t]];
        sw[h][t] = (e >= 0.f) ? e : 0.2f * e;
    }
    __syncthreads();

    if (wid < nheads) {
        int h = wid;
        float m = -FLT_MAX;
        for (int t = lane; t < c; t += 32) m = fmaxf(m, sw[h][t]);
#pragma unroll
        for (int o = 16; o > 0; o >>= 1) m = fmaxf(m, __shfl_xor_sync(0xFFFFFFFFu, m, o));
        float s = 0.f;
        for (int t = lane; t < c; t += 32) { float ex = expf(sw[h][t] - m); sw[h][t] = ex; s += ex; }
#pragma unroll
        for (int o = 16; o > 0; o >>= 1) s += __shfl_xor_sync(0xFFFFFFFFu, s, o);
        if (lane == 0) hs[h] = s;
    }
    __syncthreads();

    for (int q = tid; q < nheads*c; q += 256) {
        int h = q / c, t = q - h*c;
        sw[h][t] /= hs[h];
    }
    __syncthreads();

    for (int h = 0; h < nheads; h++) {
        float acc = 0.f;
#pragma unroll 4
        for (int t = 0; t < c; t++)
            acc = fmaf(sw[h][t], Wh[(size_t)sidx[t]*rowStride + h*HID + tid], acc);
        out[(size_t)i*rowStride + h*HID + tid] = (acc > 0.f) ? acc : expm1f(acc);
    }
}

// ---------------- repack W + tf32 split, z-batched ----------------
__global__ void repack_W2(const float* __restrict__ W0, float* __restrict__ Whi0,
                          float* __restrict__ Wlo0,
                          const float* __restrict__ W1, float* __restrict__ Whi1,
                          float* __restrict__ Wlo1)
{
    const float* W = blockIdx.z ? W1 : W0;
    float* Whi = blockIdx.z ? Whi1 : Whi0;
    float* Wlo = blockIdx.z ? Wlo1 : Wlo0;
    int i = blockIdx.x * blockDim.x + threadIdx.x;
    if (i >= DIN*NH*HID) return;
    int d = i / (NH*HID);
    int r = i % (NH*HID);
    int h = r / HID;
    int f = r % HID;
    float v = W[(size_t)h*DIN*HID + (size_t)d*HID + f];
    float hi = tf32r(v);
    Whi[i] = hi;
    Wlo[i] = tf32r(v - hi);
}

__global__ void s1s2_kernel2(const float* __restrict__ WhA, const float* __restrict__ aA,
                             float* __restrict__ s1A, float* __restrict__ s2A,
                             const float* __restrict__ WhB, const float* __restrict__ aB,
                             float* __restrict__ s1B, float* __restrict__ s2B,
                             int rowStride)
{
    const float* Wh = blockIdx.z ? WhB : WhA;
    const float* a  = blockIdx.z ? aB : aA;
    float* s1 = blockIdx.z ? s1B : s1A;
    float* s2 = blockIdx.z ? s2B : s2A;
    int i = blockIdx.x, h = blockIdx.y, f = threadIdx.x;
    float w = Wh[(size_t)i*rowStride + h*HID + f];
    float v1 = w * a[h*2*HID + f];
    float v2 = w * a[h*2*HID + HID + f];
    __shared__ float r1[256], r2[256];
    r1[f] = v1; r2[f] = v2; __syncthreads();
    for (int st = 128; st > 0; st >>= 1) {
        if (f < st) { r1[f] += r1[f+st]; r2[f] += r2[f+st]; }
        __syncthreads();
    }
    if (f == 0) { s1[h*NN + i] = r1[0]; s2[h*NN + i] = r2[0]; }
}

// ---------------- MLP pieces (PROVEN) ----------------
__global__ void concat_kernel()
{
    int i = blockIdx.x, c = threadIdx.x;
    g_pair[(size_t)i*512 + c] = (c < HID) ? g_embU[(size_t)i*HID + c]
                                          : g_embF[(size_t)i*HID + (c - HID)];
}

__global__ void mlp_final_kernel(const float* __restrict__ act, const float* __restrict__ W,
                                 const float* __restrict__ b, float* __restrict__ out)
{
    int i = blockIdx.x, tid = threadIdx.x;
    float v = act[(size_t)i*128 + tid] * W[tid];
    __shared__ float r[128];
    r[tid] = v; __syncthreads();
    for (int st = 64; st > 0; st >>= 1) { if (tid < st) r[tid] += r[tid+st]; __syncthreads(); }
    if (tid == 0) out[i] = r[0] + b[0];
}

// ---------------- host launch ----------------
template <typename T>
static T* sym(const void* s)
{
    void* p = nullptr;
    cudaGetSymbolAddress(&p, s);
    return (T*)p;
}

extern "C" void kernel_launch(void* const* d_in, const int* in_sizes, int n_in,
                              void* d_out, int out_size)
{
    const float* user_nodes = (const float*)d_in[0];
    const float* food_nodes = (const float*)d_in[1];
    const float* user_W_h   = (const float*)d_in[2];
    const float* user_a_h   = (const float*)d_in[3];
    const float* user_W_o   = (const float*)d_in[4];
    const float* user_a_o   = (const float*)d_in[5];
    const float* food_W_h   = (const float*)d_in[6];
    const float* food_a_h   = (const float*)d_in[7];
    const float* food_W_o   = (const float*)d_in[8];
    const float* food_a_o   = (const float*)d_in[9];
    const float* mlp_W0 = (const float*)d_in[10];
    const float* mlp_b0 = (const float*)d_in[11];
    const float* mlp_W1 = (const float*)d_in[12];
    const float* mlp_b1 = (const float*)d_in[13];
    const float* mlp_W2 = (const float*)d_in[14];
    const float* mlp_b2 = (const float*)d_in[15];
    const float* mlp_W3 = (const float*)d_in[16];
    const float* mlp_b3 = (const float*)d_in[17];
    float* out = (float*)d_out;

    float* pZero  = sym<float>(g_zero);
    float* pSqU   = sym<float>(g_sqU);
    float* pXnF   = sym<float>(g_XnF);
    float* pSimU  = sym<float>(g_simU);
    float* pSimF  = sym<float>(g_simF);
    int*   pTidxU = sym<int>(g_tidxU);
    float* pTvalU = sym<float>(g_tvalU);
    int*   pTidxF = sym<int>(g_tidxF);
    float* pTvalF = sym<float>(g_tvalF);
    unsigned char* pMaskU = sym<unsigned char>(g_maskU);
    unsigned char* pMaskF = sym<unsigned char>(g_maskF);
    int*   pNbrU = sym<int>(g_nbrU);
    int*   pCntU = sym<int>(g_cntU);
    int*   pNbrF = sym<int>(g_nbrF);
    int*   pCntF = sym<int>(g_cntF);
    float* pUhi = sym<float>(g_uhi);  float* pUlo = sym<float>(g_ulo);
    float* pFhi = sym<float>(g_fhi);  float* pFlo = sym<float>(g_flo);
    float* pXhi = sym<float>(g_xhi);  float* pXlo = sym<float>(g_xlo);
    float* pWhiU = sym<float>(g_WhiU); float* pWloU = sym<float>(g_WloU);
    float* pWhiF = sym<float>(g_WhiF); float* pWloF = sym<float>(g_WloF);
    float* pWhU  = sym<float>(g_WhU);
    float* pWhF  = sym<float>(g_WhF);
    float* pS1U  = sym<float>(g_s1U);
    float* pS2U  = sym<float>(g_s2U);
    float* pS1F  = sym<float>(g_s1F);
    float* pS2F  = sym<float>(g_s2F);
    float* pHidU = sym<float>(g_hidU);
    float* pHidF = sym<float>(g_hidF);
    float* pWhoU = sym<float>(g_WhoU);
    float* pWhoF = sym<float>(g_WhoF);
    float* pS1oU = sym<float>(g_s1oU);
    float* pS2oU = sym<float>(g_s2oU);
    float* pS1oF = sym<float>(g_s1oF);
    float* pS2oF = sym<float>(g_s2oF);
    float* pEmbU = sym<float>(g_embU);
    float* pEmbF = sym<float>(g_embF);
    float* pPair = sym<float>(g_pair);
    float* pAct0 = sym<float>(g_act0);
    float* pAct1 = sym<float>(g_act1);
    float* pAct2 = sym<float>(g_act2);

    const int NTRI = (NN/128) * (NN/128 + 1) / 2;   // 136 upper-tri tiles

    // ---- graph build + hidden-layer GEMMs in ONE mma launch (4th kernel: profiled) ----
    prep_kernel<<<dim3(NN,1,2), 256>>>(user_nodes, pSqU, food_nodes, pXnF);                       // 1
    split3_kernel<<<dim3(NN*DIN/4/256,1,3), 256>>>(user_nodes, pUhi, pUlo,
                                                   food_nodes, pFhi, pFlo,
                                                   pXnF, pXhi, pXlo);                             // 2
    repack_W2<<<dim3((DIN*NH*HID+255)/256,1,2), 256>>>(user_W_h, pWhiU, pWloU,
                                                       food_W_h, pWhiF, pWloF);                   // 3
    megamma<<<dim3(NTRI,1,4), 256>>>(pUhi, pUlo, pXhi, pXlo, pFhi, pFlo,
                                     pWhiU, pWloU, pWhiF, pWloF,
                                     pSimU, pSimF, pWhU, pWhF, pSqU, pZero);                      // 4 (profiled)
    top6_onepass<<<dim3(NN,1,2), 128>>>(pSimU, pSimF, pTidxU, pTvalU, pTidxF, pTvalF);            // 5

    clear_masks<<<(NN*NN/4)/256, 256>>>();
    mark_kernel2<<<dim3((NN+255)/256,1,2), 256>>>(pTidxU, pTvalU, pMaskU,
                                                  pTidxF, pTvalF, pMaskF);
    collect_kernel2<<<dim3(NN*32/256,1,2), 256>>>(pMaskU, pNbrU, pCntU,
                                                  pMaskF, pNbrF, pCntF);

    // ---- GAT hidden layer attention ----
    s1s2_kernel2<<<dim3(NN, NH, 2), 256>>>(pWhU, user_a_h, pS1U, pS2U,
                                           pWhF, food_a_h, pS1F, pS2F, NH*HID);
    att_agg2<<<dim3(NN,1,2), 256>>>(pWhU, pS1U, pS2U, pNbrU, pCntU, pHidU,
                                    pWhF, pS1F, pS2F, pNbrF, pCntF, pHidF,
                                    NH*HID, NH);

    // ---- GAT output layer (user & food batched; SIMT) ----
    sgemm2<false, 0, 64,64,4,4><<<dim3(HID/64, NN/64, 2), 256>>>(
        pHidU, user_W_o, pWhoU, nullptr,
        pHidF, food_W_o, pWhoF, nullptr,
        NN, HID, NH*HID, NH*HID, HID, HID);
    s1s2_kernel2<<<dim3(NN, 1, 2), 256>>>(pWhoU, user_a_o, pS1oU, pS2oU,
                                          pWhoF, food_a_o, pS1oF, pS2oF, HID);
    att_agg2<<<dim3(NN,1,2), 256>>>(pWhoU, pS1oU, pS2oU, pNbrU, pCntU, pEmbU,
                                    pWhoF, pS1oF, pS2oF, pNbrF, pCntF, pEmbF,
                                    HID, 1);

    // ---- MLP (SIMT) ----
    concat_kernel<<<NN, 512>>>();
    sgemm2<false, 2, 64,64,4,4><<<dim3(512/64, NN/64, 1), 256>>>(
        pPair, mlp_W0, pAct0, mlp_b0,
        pPair, mlp_W0, pAct0, mlp_b0,
        NN, 512, 512, 512, 512, 512);
    sgemm2<false, 2, 64,64,4,4><<<dim3(256/64, NN/64, 1), 256>>>(
        pAct0, mlp_W1, pAct1, mlp_b1,
        pAct0, mlp_W1, pAct1, mlp_b1,
        NN, 256, 512, 512, 256, 256);
    sgemm2<false, 2, 64,64,4,4><<<dim3(128/64, NN/64, 1), 256>>>(
        pAct1, mlp_W2, pAct2, mlp_b2,
        pAct1, mlp_W2, pAct2, mlp_b2,
        NN, 128, 256, 256, 128, 128);
    mlp_final_kernel<<<NN, 128>>>(pAct2, mlp_W3, mlp_b3, out);
}